// round 3
// baseline (speedup 1.0000x reference)
#include <cuda_runtime.h>

// Problem dims
#define BDIM   8
#define SDIM   96
#define DDIM   768
#define RSTEPS 24     // = R (number of refine steps AND rel_num)
#define RSEQ   8
#define TAGS   3
#define K3     2304   // 3*D
#define NK     72     // R*TAG
#define MROWS  768    // B*S
#define ENC_STRIDE (SDIM*DDIM)
#define H_STRIDE   (SDIM*K3)

// Scratch (device globals: no allocation allowed)
__device__ float g_enc[BDIM*SDIM*DDIM];   // refined encoder output
__device__ float g_Hh [BDIM*SDIM*K3];     // enc @ Wh + proj_b  (bias folded here)
__device__ float g_Ht [BDIM*SDIM*K3];     // enc @ Wt

// Packed fp32x2 FMA (sm_100+): doubles fp32 throughput vs scalar FFMA.
__device__ __forceinline__ void fma2(float2& acc, float2 a, float2 b) {
    asm("fma.rn.f32x2 %0, %1, %2, %0;"
        : "+l"(*reinterpret_cast<unsigned long long*>(&acc))
        : "l"(*reinterpret_cast<unsigned long long*>(&a)),
          "l"(*reinterpret_cast<unsigned long long*>(&b)));
}

// ---------------------------------------------------------------------------
// Kernel 1: refine.  One CTA per batch, 256 threads.
// Uses the rank-8 identity: scores_{t+1} = scores_t + G @ w_t, G = scale*A*A^T
// enc_final = enc0 + (sum_t w_t)^T @ A
// ---------------------------------------------------------------------------
__global__ __launch_bounds__(256, 1)
void refine_kernel(const float* __restrict__ enc0,
                   const float* __restrict__ rel) {
    const int b    = blockIdx.x;
    const int tid  = threadIdx.x;
    const int warp = tid >> 5;
    const int lane = tid & 31;

    __shared__ float sA [RSEQ*DDIM];   // A = rel_types[b]  (8x768)
    __shared__ float sG [RSEQ*RSEQ];   // scale * A A^T
    __shared__ float sS [RSEQ*SDIM];   // scores 8x96
    __shared__ float sW [RSEQ*SDIM];   // softmax weights
    __shared__ float sWs[RSEQ*SDIM];   // running sum of weights

    const float scale = rsqrtf((float)DDIM);

    for (int i = tid; i < RSEQ*DDIM; i += 256) sA[i]  = rel[b*RSEQ*DDIM + i];
    for (int i = tid; i < RSEQ*SDIM; i += 256) sWs[i] = 0.f;
    __syncthreads();

    // G = scale * A A^T : 64 pairs, 4 threads each
    {
        int pair = tid >> 2, part = tid & 3;
        int r = pair >> 3, q = pair & 7;
        float s = 0.f;
        for (int c = part; c < DDIM; c += 4)
            s += sA[r*DDIM + c] * sA[q*DDIM + c];
        s += __shfl_down_sync(0xffffffffu, s, 2, 4);
        s += __shfl_down_sync(0xffffffffu, s, 1, 4);
        if (part == 0) sG[pair] = s * scale;
    }

    // scores0 = scale * A @ enc0[b]^T  — each warp handles rows s0 = warp, warp+8, ...
    for (int s0 = warp; s0 < SDIM; s0 += 8) {
        const float* erow = enc0 + (b*SDIM + s0)*DDIM;
        float p[8];
        #pragma unroll
        for (int r = 0; r < 8; r++) p[r] = 0.f;
        for (int c = lane; c < DDIM; c += 32) {
            float e = erow[c];
            #pragma unroll
            for (int r = 0; r < 8; r++) p[r] += sA[r*DDIM + c] * e;
        }
        #pragma unroll
        for (int r = 0; r < 8; r++) {
            float v = p[r];
            #pragma unroll
            for (int o = 16; o > 0; o >>= 1) v += __shfl_down_sync(0xffffffffu, v, o);
            if (lane == 0) sS[r*SDIM + s0] = v * scale;
        }
    }
    __syncthreads();

    // 24 iterations: w = softmax(scores); Wsum += w; scores += G @ w
    for (int t = 0; t < RSTEPS; t++) {
        {   // warp r owns score row r (96 vals = 3 per lane)
            const float* row = sS + warp*SDIM;
            float v0 = row[lane], v1 = row[lane+32], v2 = row[lane+64];
            float m = fmaxf(v0, fmaxf(v1, v2));
            #pragma unroll
            for (int o = 16; o > 0; o >>= 1) m = fmaxf(m, __shfl_xor_sync(0xffffffffu, m, o));
            float e0 = __expf(v0 - m), e1 = __expf(v1 - m), e2 = __expf(v2 - m);
            float sum = e0 + e1 + e2;
            #pragma unroll
            for (int o = 16; o > 0; o >>= 1) sum += __shfl_xor_sync(0xffffffffu, sum, o);
            float inv = 1.f / sum;
            sW [warp*SDIM + lane]      = e0*inv;
            sW [warp*SDIM + lane+32]   = e1*inv;
            sW [warp*SDIM + lane+64]   = e2*inv;
            sWs[warp*SDIM + lane]     += e0*inv;
            sWs[warp*SDIM + lane+32]  += e1*inv;
            sWs[warp*SDIM + lane+64]  += e2*inv;
        }
        __syncthreads();
        for (int idx = tid; idx < RSEQ*SDIM; idx += 256) {
            int r = idx / SDIM, s = idx - r*SDIM;
            float acc = sS[idx];
            #pragma unroll
            for (int q = 0; q < 8; q++) acc += sG[r*8 + q] * sW[q*SDIM + s];
            sS[idx] = acc;
        }
        __syncthreads();
    }

    // enc_final = enc0 + Wsum^T @ A
    for (int idx = tid; idx < ENC_STRIDE; idx += 256) {
        int s = idx / DDIM, c = idx - s*DDIM;
        float v = enc0[b*ENC_STRIDE + idx];
        #pragma unroll
        for (int r = 0; r < 8; r++) v += sWs[r*SDIM + s] * sA[r*DDIM + c];
        g_enc[b*ENC_STRIDE + idx] = v;
    }
}

// ---------------------------------------------------------------------------
// Kernel 2: H = enc @ proj_W  (z=0: Wh rows [0,768) + proj_b -> g_Hh,
//                              z=1: Wt rows [768,1536)       -> g_Ht)
// M=768, K=768, N=2304. Tiles 64x128x16, 256 threads, thread tile 4x8 (FFMA2).
// ---------------------------------------------------------------------------
#define GBM 64
#define GBN 128
#define GBK 16

__global__ __launch_bounds__(256, 2)
void hgemm_kernel(const float* __restrict__ pW,
                  const float* __restrict__ pb) {
    const int n0 = blockIdx.x * GBN;
    const int m0 = blockIdx.y * GBM;
    const int z  = blockIdx.z;
    const float* W = pW + (z ? (size_t)DDIM*K3 : 0);
    float* O = z ? g_Ht : g_Hh;
    const int tid = threadIdx.x;
    const int tm  = (tid & 15) << 2;   // 16 groups * 4 rows
    const int tn  = (tid >> 4) << 3;   // 16 groups * 8 cols

    __shared__ float sA[GBK][GBM + 4];   // stride 68 (16B-aligned rows)
    __shared__ float sB[GBK][GBN + 2];   // stride 130 (8B-aligned rows)

    float2 acc[4][4];
    #pragma unroll
    for (int i = 0; i < 4; i++)
        #pragma unroll
        for (int j = 0; j < 4; j++) acc[i][j] = make_float2(0.f, 0.f);

    for (int k0 = 0; k0 < DDIM; k0 += GBK) {
        #pragma unroll
        for (int it = 0; it < 4; it++) {
            int idx = tid + 256*it;
            int kk = idx & 15, m = idx >> 4;
            sA[kk][m] = g_enc[(size_t)(m0 + m)*DDIM + k0 + kk];
        }
        #pragma unroll
        for (int it = 0; it < 8; it++) {
            int idx = tid + 256*it;
            int nn = idx & 127, kk = idx >> 7;
            sB[kk][nn] = W[(size_t)(k0 + kk)*K3 + n0 + nn];
        }
        __syncthreads();
        #pragma unroll
        for (int kk = 0; kk < GBK; kk++) {
            float4 a4 = *(const float4*)&sA[kk][tm];
            float2 b2[4];
            #pragma unroll
            for (int q = 0; q < 4; q++) b2[q] = *(const float2*)&sB[kk][tn + 2*q];
            float am[4] = {a4.x, a4.y, a4.z, a4.w};
            #pragma unroll
            for (int mi = 0; mi < 4; mi++) {
                float2 ad = make_float2(am[mi], am[mi]);
                #pragma unroll
                for (int q = 0; q < 4; q++) fma2(acc[mi][q], ad, b2[q]);
            }
        }
        __syncthreads();
    }

    #pragma unroll
    for (int mi = 0; mi < 4; mi++) {
        float* orow = O + (size_t)(m0 + tm + mi)*K3 + n0 + tn;
        #pragma unroll
        for (int q = 0; q < 4; q++) {
            float2 v = acc[mi][q];
            if (z == 0) { v.x += pb[n0 + tn + 2*q]; v.y += pb[n0 + tn + 2*q + 1]; }
            *(float2*)(orow + 2*q) = v;
        }
    }
}

// ---------------------------------------------------------------------------
// Kernel 3: fused pair GEMM.
// CTA = (i, b): T[j,k] = sum_c relu(Hh[b,i,c] + Ht[b,j,c]) * rel_W[c,k] + rel_b[k]
// Output tile 96(j) x 72(k), K=2304 streamed in chunks of 32.
// 96 threads, thread tile 12(j) x 6(k) via FFMA2 (6 j-pairs).
// Writes out[b, tag, r, i, j] with k = r*3+tag.
// ---------------------------------------------------------------------------
#define KC  32
#define PTJ 12
#define PTK 6

__global__ __launch_bounds__(96, 4)
void pair_kernel(const float* __restrict__ relW,
                 const float* __restrict__ relb,
                 float* __restrict__ out) {
    const int i   = blockIdx.x;
    const int b   = blockIdx.y;
    const int tid = threadIdx.x;             // 96
    const int tj  = (tid & 7) * PTJ;         // 8 groups * 12 = 96
    const int tk  = (tid >> 3) * PTK;        // 12 groups * 6 = 72

    __shared__ float sAct[KC][SDIM + 2];     // row stride 98 (8B aligned)
    __shared__ float sW  [KC][NK + 2];       // row stride 74
    __shared__ float sHh [KC];

    const float* HhRow = g_Hh + (size_t)(b*SDIM + i)*K3;
    const float* HtB   = g_Ht + (size_t)b*H_STRIDE;

    float2 acc[6][PTK];
    #pragma unroll
    for (int p = 0; p < 6; p++)
        #pragma unroll
        for (int q = 0; q < PTK; q++) acc[p][q] = make_float2(0.f, 0.f);

    for (int c0 = 0; c0 < K3; c0 += KC) {
        __syncthreads();                       // smem reuse guard
        if (tid < KC) sHh[tid] = HhRow[c0 + tid];
        #pragma unroll 4
        for (int idx = tid; idx < SDIM*KC; idx += 96) {
            int cc = idx & (KC-1); int j = idx >> 5;
            sAct[cc][j] = HtB[(size_t)j*K3 + c0 + cc];
        }
        #pragma unroll 4
        for (int idx = tid; idx < KC*NK; idx += 96) {
            int k = idx % NK; int cc = idx / NK;
            sW[cc][k] = relW[(size_t)(c0 + cc)*NK + k];
        }
        __syncthreads();
        // activation in place: act = relu(ht + hh)
        #pragma unroll 4
        for (int idx = tid; idx < SDIM*KC; idx += 96) {
            int j = idx % SDIM; int cc = idx / SDIM;
            float hh = sHh[cc];
            sAct[cc][j] = fmaxf(sAct[cc][j] + hh, 0.f);
        }
        __syncthreads();
        #pragma unroll 4
        for (int cc = 0; cc < KC; cc++) {
            float2 a[6];
            #pragma unroll
            for (int p = 0; p < 6; p++) a[p] = *(const float2*)&sAct[cc][tj + 2*p];
            #pragma unroll
            for (int q = 0; q < PTK; q++) {
                float wv = sW[cc][tk + q];
                float2 wd = make_float2(wv, wv);
                #pragma unroll
                for (int p = 0; p < 6; p++) fma2(acc[p][q], a[p], wd);
            }
        }
    }

    // epilogue: bias + scatter into transposed output layout
    #pragma unroll
    for (int q = 0; q < PTK; q++) {
        int k = tk + q;
        float bias = relb[k];
        int r = k / TAGS, tg = k - r*TAGS;
        float* op = out + ((((size_t)b*TAGS + tg)*RSTEPS + r)*SDIM + i)*SDIM + tj;
        #pragma unroll
        for (int p = 0; p < 6; p++) {
            float2 v = acc[p][q];
            v.x += bias; v.y += bias;
            *(float2*)(op + 2*p) = v;
        }
    }
}

// ---------------------------------------------------------------------------
extern "C" void kernel_launch(void* const* d_in, const int* in_sizes, int n_in,
                              void* d_out, int out_size) {
    const float* enc0 = (const float*)d_in[0];   // [8,96,768]
    const float* rel  = (const float*)d_in[1];   // [24,8,768]
    const float* pW   = (const float*)d_in[2];   // [1536,2304]
    const float* pb   = (const float*)d_in[3];   // [2304]
    const float* rW   = (const float*)d_in[4];   // [2304,72]
    const float* rb   = (const float*)d_in[5];   // [72]
    float* out = (float*)d_out;                  // [8,3,24,96,96]

    refine_kernel<<<BDIM, 256>>>(enc0, rel);
    hgemm_kernel<<<dim3(K3/GBN, MROWS/GBM, 2), 256>>>(pW, pb);
    pair_kernel<<<dim3(SDIM, BDIM), 96>>>(rW, rb, out);
}

// round 7
// speedup vs baseline: 1.4250x; 1.4250x over previous
#include <cuda_runtime.h>
#include <cuda_bf16.h>
#include <cstdint>

// Problem dims
#define BDIM   8
#define SDIM   96
#define DDIM   768
#define RSTEPS 24
#define RSEQ   8
#define TAGS   3
#define K3     2304   // 3*D
#define NK     72     // R*TAG
#define MROWS  768    // B*S
#define ENC_STRIDE (SDIM*DDIM)
#define MPB    (SDIM*SDIM)   // 9216 rows per batch in pair GEMM

// ---- scratch (device globals; no allocation allowed) ----
__device__ float g_enc[BDIM*SDIM*DDIM];
__device__ float g_Hh [BDIM*SDIM*K3];     // enc @ Wh + proj_b
__device__ float g_Ht [BDIM*SDIM*K3];     // enc @ Wt
__device__ float g_G  [BDIM*64];
__device__ float g_S  [BDIM*RSEQ*SDIM];
__device__ float g_Ws [BDIM*RSEQ*SDIM];
__device__ __align__(16) __nv_bfloat16 g_rwhi[NK*K3];   // relW^T hi, [n][k]
__device__ __align__(16) __nv_bfloat16 g_rwlo[NK*K3];   // relW^T lo

__device__ __forceinline__ uint32_t smem_u32(const void* p) {
    uint32_t a;
    asm("{ .reg .u64 t; cvta.to.shared.u64 t, %1; cvt.u32.u64 %0, t; }" : "=r"(a) : "l"(p));
    return a;
}
__device__ __forceinline__ void fma2(float2& acc, float2 a, float2 b) {
    asm("fma.rn.f32x2 %0, %1, %2, %0;"
        : "+l"(*reinterpret_cast<unsigned long long*>(&acc))
        : "l"(*reinterpret_cast<unsigned long long*>(&a)),
          "l"(*reinterpret_cast<unsigned long long*>(&b)));
}
__device__ __forceinline__ void ldsm_x4(uint32_t* r, uint32_t addr) {
    asm volatile("ldmatrix.sync.aligned.m8n8.x4.shared.b16 {%0,%1,%2,%3}, [%4];"
        : "=r"(r[0]), "=r"(r[1]), "=r"(r[2]), "=r"(r[3]) : "r"(addr));
}
__device__ __forceinline__ void ldsm_x2(uint32_t* r, uint32_t addr) {
    asm volatile("ldmatrix.sync.aligned.m8n8.x2.shared.b16 {%0,%1}, [%2];"
        : "=r"(r[0]), "=r"(r[1]) : "r"(addr));
}
__device__ __forceinline__ void mma_bf16(float* d, const uint32_t* a, const uint32_t* b) {
    asm volatile("mma.sync.aligned.m16n8k16.row.col.f32.bf16.bf16.f32 "
        "{%0,%1,%2,%3}, {%4,%5,%6,%7}, {%8,%9}, {%0,%1,%2,%3};"
        : "+f"(d[0]), "+f"(d[1]), "+f"(d[2]), "+f"(d[3])
        : "r"(a[0]), "r"(a[1]), "r"(a[2]), "r"(a[3]), "r"(b[0]), "r"(b[1]));
}

// ---------------------------------------------------------------------------
// refine, phase 1: per-batch G = scale*A*A^T (part 0) and scores0 (parts 1..6)
// ---------------------------------------------------------------------------
__global__ __launch_bounds__(256, 1)
void refine_pre(const float* __restrict__ enc0, const float* __restrict__ rel) {
    const int part = blockIdx.x, b = blockIdx.y;
    const int tid = threadIdx.x, warp = tid >> 5, lane = tid & 31;
    __shared__ float sA[RSEQ*DDIM];
    const float scale = rsqrtf((float)DDIM);

    for (int i = tid; i < RSEQ*DDIM; i += 256) sA[i] = rel[b*RSEQ*DDIM + i];
    __syncthreads();

    if (part == 0) {
        int pair = tid >> 2, pt = tid & 3;
        int r = pair >> 3, q = pair & 7;
        float s = 0.f;
        for (int c = pt; c < DDIM; c += 4) s += sA[r*DDIM + c] * sA[q*DDIM + c];
        s += __shfl_down_sync(0xffffffffu, s, 2, 4);
        s += __shfl_down_sync(0xffffffffu, s, 1, 4);
        if (pt == 0) g_G[b*64 + pair] = s * scale;
    } else {
        int rowbase = (part - 1) * 16;
        for (int sl = warp; sl < 16; sl += 8) {
            int row = rowbase + sl;
            const float* erow = enc0 + (b*SDIM + row)*DDIM;
            float p[8];
            #pragma unroll
            for (int r = 0; r < 8; r++) p[r] = 0.f;
            for (int c = lane; c < DDIM; c += 32) {
                float e = erow[c];
                #pragma unroll
                for (int r = 0; r < 8; r++) p[r] += sA[r*DDIM + c] * e;
            }
            #pragma unroll
            for (int r = 0; r < 8; r++) {
                float v = p[r];
                #pragma unroll
                for (int o = 16; o > 0; o >>= 1) v += __shfl_down_sync(0xffffffffu, v, o);
                if (lane == 0) g_S[b*RSEQ*SDIM + r*SDIM + row] = v * scale;
            }
        }
    }
}

// ---------------------------------------------------------------------------
// refine, phase 2: 24-step scan on [8x96] scores. grid B, 256 threads.
// ---------------------------------------------------------------------------
__global__ __launch_bounds__(256, 1)
void refine_scan() {
    const int b = blockIdx.x, tid = threadIdx.x, warp = tid >> 5, lane = tid & 31;
    __shared__ float sG[64], sS[RSEQ*SDIM], sW[RSEQ*SDIM], sWs[RSEQ*SDIM];
    if (tid < 64) sG[tid] = g_G[b*64 + tid];
    for (int i = tid; i < RSEQ*SDIM; i += 256) { sS[i] = g_S[b*RSEQ*SDIM + i]; sWs[i] = 0.f; }
    __syncthreads();

    for (int t = 0; t < RSTEPS; t++) {
        {
            const float* row = sS + warp*SDIM;
            float v0 = row[lane], v1 = row[lane+32], v2 = row[lane+64];
            float m = fmaxf(v0, fmaxf(v1, v2));
            #pragma unroll
            for (int o = 16; o > 0; o >>= 1) m = fmaxf(m, __shfl_xor_sync(0xffffffffu, m, o));
            float e0 = __expf(v0 - m), e1 = __expf(v1 - m), e2 = __expf(v2 - m);
            float sum = e0 + e1 + e2;
            #pragma unroll
            for (int o = 16; o > 0; o >>= 1) sum += __shfl_xor_sync(0xffffffffu, sum, o);
            float inv = 1.f / sum;
            sW [warp*SDIM + lane]    = e0*inv;
            sW [warp*SDIM + lane+32] = e1*inv;
            sW [warp*SDIM + lane+64] = e2*inv;
            sWs[warp*SDIM + lane]    += e0*inv;
            sWs[warp*SDIM + lane+32] += e1*inv;
            sWs[warp*SDIM + lane+64] += e2*inv;
        }
        __syncthreads();
        for (int idx = tid; idx < RSEQ*SDIM; idx += 256) {
            int r = idx / SDIM, s = idx - r*SDIM;
            float acc = sS[idx];
            #pragma unroll
            for (int q = 0; q < 8; q++) acc += sG[r*8 + q] * sW[q*SDIM + s];
            sS[idx] = acc;
        }
        __syncthreads();
    }
    for (int i = tid; i < RSEQ*SDIM; i += 256) g_Ws[b*RSEQ*SDIM + i] = sWs[i];
}

// ---------------------------------------------------------------------------
// refine, phase 3: enc = enc0 + Ws^T @ A. grid (12, B), 256 threads.
// ---------------------------------------------------------------------------
__global__ __launch_bounds__(256, 2)
void refine_post(const float* __restrict__ enc0, const float* __restrict__ rel) {
    const int b = blockIdx.y, s0 = blockIdx.x * 8;
    const int tid = threadIdx.x;
    __shared__ float sWs[8*8];
    __shared__ float sA[RSEQ*DDIM];
    if (tid < 64) {
        int sl = tid >> 3, r = tid & 7;
        sWs[sl*8 + r] = g_Ws[b*RSEQ*SDIM + r*SDIM + s0 + sl];
    }
    for (int i = tid; i < RSEQ*DDIM; i += 256) sA[i] = rel[b*RSEQ*DDIM + i];
    __syncthreads();
    for (int idx = tid; idx < 8*DDIM; idx += 256) {
        int sl = idx / DDIM, c = idx - sl*DDIM;
        int off = (b*SDIM + s0 + sl)*DDIM + c;
        float v = enc0[off];
        #pragma unroll
        for (int r = 0; r < 8; r++) v += sWs[sl*8 + r] * sA[r*DDIM + c];
        g_enc[off] = v;
    }
}

// ---------------------------------------------------------------------------
// prep: relW^T split into bf16 hi/lo, layout [n][k]
// ---------------------------------------------------------------------------
__global__ __launch_bounds__(256, 4)
void prep_relw(const float* __restrict__ relW) {
    int idx = blockIdx.x * 256 + threadIdx.x;
    if (idx >= NK*K3) return;
    int n = idx / K3, k = idx - n*K3;
    float v = relW[(size_t)k*NK + n];
    __nv_bfloat16 hi = __float2bfloat16(v);
    __nv_bfloat16 lo = __float2bfloat16(v - __bfloat162float(hi));
    g_rwhi[idx] = hi;
    g_rwlo[idx] = lo;
}

// ---------------------------------------------------------------------------
// hgemm: H = enc @ proj_W (fp32 FFMA2, unchanged from passing R3 version)
// ---------------------------------------------------------------------------
#define GBM 64
#define GBN 128
#define GBK 16

__global__ __launch_bounds__(256, 2)
void hgemm_kernel(const float* __restrict__ pW, const float* __restrict__ pb) {
    const int n0 = blockIdx.x * GBN;
    const int m0 = blockIdx.y * GBM;
    const int z  = blockIdx.z;
    const float* W = pW + (z ? (size_t)DDIM*K3 : 0);
    float* O = z ? g_Ht : g_Hh;
    const int tid = threadIdx.x;
    const int tm  = (tid & 15) << 2;
    const int tn  = (tid >> 4) << 3;

    __shared__ float sA[GBK][GBM + 4];
    __shared__ float sB[GBK][GBN + 2];

    float2 acc[4][4];
    #pragma unroll
    for (int i = 0; i < 4; i++)
        #pragma unroll
        for (int j = 0; j < 4; j++) acc[i][j] = make_float2(0.f, 0.f);

    for (int k0 = 0; k0 < DDIM; k0 += GBK) {
        #pragma unroll
        for (int it = 0; it < 4; it++) {
            int idx = tid + 256*it;
            int kk = idx & 15, m = idx >> 4;
            sA[kk][m] = g_enc[(size_t)(m0 + m)*DDIM + k0 + kk];
        }
        #pragma unroll
        for (int it = 0; it < 8; it++) {
            int idx = tid + 256*it;
            int nn = idx & 127, kk = idx >> 7;
            sB[kk][nn] = W[(size_t)(k0 + kk)*K3 + n0 + nn];
        }
        __syncthreads();
        #pragma unroll
        for (int kk = 0; kk < GBK; kk++) {
            float4 a4 = *(const float4*)&sA[kk][tm];
            float2 b2[4];
            #pragma unroll
            for (int q = 0; q < 4; q++) b2[q] = *(const float2*)&sB[kk][tn + 2*q];
            float am[4] = {a4.x, a4.y, a4.z, a4.w};
            #pragma unroll
            for (int mi = 0; mi < 4; mi++) {
                float2 ad = make_float2(am[mi], am[mi]);
                #pragma unroll
                for (int q = 0; q < 4; q++) fma2(acc[mi][q], ad, b2[q]);
            }
        }
        __syncthreads();
    }
    #pragma unroll
    for (int mi = 0; mi < 4; mi++) {
        float* orow = O + (size_t)(m0 + tm + mi)*K3 + n0 + tn;
        #pragma unroll
        for (int q = 0; q < 4; q++) {
            float2 v = acc[mi][q];
            if (z == 0) { v.x += pb[n0 + tn + 2*q]; v.y += pb[n0 + tn + 2*q + 1]; }
            *(float2*)(orow + 2*q) = v;
        }
    }
}

// ---------------------------------------------------------------------------
// pair GEMM via mma.sync (HMMA, bf16 3-pass error-compensated).
// CTA = 128 gm-rows x N=72, K chunked by 32. 128 threads = 4 warps, warp m32 x n72.
// Static smem only (33.5 KB) -> 3 CTAs/SM, no dynamic-smem attribute needed.
// ---------------------------------------------------------------------------
#define PKC     32                 // K per chunk
#define PNCH    (K3/PKC)           // 72 chunks
#define ROWH    40                 // smem row stride in halves (80B: ldmatrix conflict-free)

__global__ __launch_bounds__(128, 3)
void pair_kernel(const float* __restrict__ relb, float* __restrict__ out) {
    __shared__ __align__(16) __nv_bfloat16 sAhi[128*ROWH];
    __shared__ __align__(16) __nv_bfloat16 sAlo[128*ROWH];
    __shared__ __align__(16) __nv_bfloat16 sWhi[NK*ROWH];
    __shared__ __align__(16) __nv_bfloat16 sWlo[NK*ROWH];
    __shared__ uint32_t sHtOff[128];
    __shared__ uint32_t sHhOff[128];

    const int tid = threadIdx.x, wid = tid >> 5, lane = tid & 31;
    const int gm0 = blockIdx.x * 128;
    const int b   = blockIdx.x / (MPB/128);     // 72 tiles per batch; tiles never straddle b

    // precompute per-row source offsets (rows fixed across all chunks)
    {
        int gm = gm0 + tid;
        int m = gm - b*MPB;
        int i = m / SDIM, j = m - i*SDIM;
        sHtOff[tid] = (uint32_t)(b*SDIM + j) * K3;
        sHhOff[tid] = (uint32_t)(b*SDIM + i) * K3;
    }

    float acc[2][9][4];
    #pragma unroll
    for (int t = 0; t < 2; t++)
        #pragma unroll
        for (int nt = 0; nt < 9; nt++)
            #pragma unroll
            for (int q = 0; q < 4; q++) acc[t][nt][q] = 0.f;

    uint32_t* sAhiU = (uint32_t*)sAhi;
    uint32_t* sAloU = (uint32_t*)sAlo;
    uint32_t* sWhiU = (uint32_t*)sWhi;
    uint32_t* sWloU = (uint32_t*)sWlo;
    const uint32_t* rwhiU = (const uint32_t*)g_rwhi;
    const uint32_t* rwloU = (const uint32_t*)g_rwlo;

    // ldmatrix base addresses (computed once)
    const uint32_t aRow = (uint32_t)(wid*32 + (lane & 15));
    const uint32_t aColH = (uint32_t)((lane >> 4) * 8);     // +0 or +8 halves
    const uint32_t aHiBase = smem_u32(sAhi);
    const uint32_t aLoBase = smem_u32(sAlo);
    const uint32_t bRowL = (uint32_t)(lane & 7);
    const uint32_t bColH = (uint32_t)(((lane >> 3) & 1) * 8);
    const uint32_t bHiBase = smem_u32(sWhi);
    const uint32_t bLoBase = smem_u32(sWlo);

    for (int chunk = 0; chunk < PNCH; chunk++) {
        const int c0 = chunk * PKC;
        __syncthreads();   // protect smem from previous iteration's readers

        // load W chunk: 72 n-rows x 16 u32 (hi and lo)
        #pragma unroll
        for (int it = 0; it < 9; it++) {
            int idx = tid + it*128;               // 0..1151
            int n = idx >> 4, cu = idx & 15;
            uint32_t src = ((uint32_t)n*K3 + (uint32_t)c0) >> 1;
            uint32_t dst = (uint32_t)n*(ROWH/2) + cu;
            sWhiU[dst] = rwhiU[src + cu];
            sWloU[dst] = rwloU[src + cu];
        }
        // build act chunk: 128 rows x 16 u32, act = relu(Hh[i]+Ht[j]) -> bf16 hi/lo
        #pragma unroll
        for (int it = 0; it < 16; it++) {
            int idx = tid + it*128;               // 0..2047
            int row = idx >> 4, cu = idx & 15;
            int coff = c0 + cu*2;
            float2 ht = *(const float2*)(g_Ht + sHtOff[row] + coff);
            float2 hh = *(const float2*)(g_Hh + sHhOff[row] + coff);
            float a0 = fmaxf(ht.x + hh.x, 0.f);
            float a1 = fmaxf(ht.y + hh.y, 0.f);
            __nv_bfloat162 hi2 = __float22bfloat162_rn(make_float2(a0, a1));
            float2 hf = __bfloat1622float2(hi2);
            __nv_bfloat162 lo2 = __float22bfloat162_rn(make_float2(a0 - hf.x, a1 - hf.y));
            uint32_t dst = (uint32_t)row*(ROWH/2) + cu;
            sAhiU[dst] = *(uint32_t*)&hi2;
            sAloU[dst] = *(uint32_t*)&lo2;
        }
        __syncthreads();

        #pragma unroll
        for (int ks = 0; ks < 2; ks++) {
            uint32_t ahi[2][4], alo[2][4];
            #pragma unroll
            for (int t = 0; t < 2; t++) {
                uint32_t aoff = ((aRow + t*16)*ROWH + ks*16 + aColH) * 2;  // bytes
                ldsm_x4(ahi[t], aHiBase + aoff);
                ldsm_x4(alo[t], aLoBase + aoff);
            }
            #pragma unroll
            for (int nt = 0; nt < 9; nt++) {
                uint32_t boff = ((nt*8 + bRowL)*ROWH + ks*16 + bColH) * 2;
                uint32_t bhi[2], blo[2];
                ldsm_x2(bhi, bHiBase + boff);
                ldsm_x2(blo, bLoBase + boff);
                #pragma unroll
                for (int t = 0; t < 2; t++) {
                    mma_bf16(acc[t][nt], ahi[t], bhi);
                    mma_bf16(acc[t][nt], ahi[t], blo);
                    mma_bf16(acc[t][nt], alo[t], bhi);
                }
            }
        }
    }

    // epilogue: scatter with bias into out[b][tag][r][i][j]
    #pragma unroll
    for (int t = 0; t < 2; t++) {
        #pragma unroll
        for (int h = 0; h < 2; h++) {
            int row = wid*32 + t*16 + (lane >> 2) + h*8;
            int m = gm0 - b*MPB + row;
            int i = m / SDIM, j = m - i*SDIM;
            #pragma unroll
            for (int nt = 0; nt < 9; nt++) {
                #pragma unroll
                for (int q = 0; q < 2; q++) {
                    int kk = nt*8 + (lane & 3)*2 + q;
                    int r = kk / TAGS, tg = kk - r*TAGS;
                    out[(((size_t)(b*TAGS + tg)*RSTEPS + r)*SDIM + i)*(size_t)SDIM + j]
                        = acc[t][nt][h*2 + q] + __ldg(relb + kk);
                }
            }
        }
    }
}

// ---------------------------------------------------------------------------
extern "C" void kernel_launch(void* const* d_in, const int* in_sizes, int n_in,
                              void* d_out, int out_size) {
    const float* enc0 = (const float*)d_in[0];
    const float* rel  = (const float*)d_in[1];
    const float* pW   = (const float*)d_in[2];
    const float* pb   = (const float*)d_in[3];
    const float* rW   = (const float*)d_in[4];
    const float* rb   = (const float*)d_in[5];
    float* out = (float*)d_out;

    refine_pre <<<dim3(7, BDIM), 256>>>(enc0, rel);
    refine_scan<<<BDIM, 256>>>();
    refine_post<<<dim3(12, BDIM), 256>>>(enc0, rel);
    prep_relw  <<<(NK*K3 + 255)/256, 256>>>(rW);
    hgemm_kernel<<<dim3(K3/GBN, MROWS/GBM, 2), 256>>>(pW, pb);
    pair_kernel<<<(BDIM*MPB)/128, 128>>>(rb, out);
}

// round 10
// speedup vs baseline: 2.6362x; 1.8499x over previous
#include <cuda_runtime.h>
#include <cuda_bf16.h>
#include <cstdint>

// Problem dims
#define BDIM   8
#define SDIM   96
#define DDIM   768
#define RSTEPS 24
#define RSEQ   8
#define TAGS   3
#define K3     2304   // 3*D
#define NK     72     // R*TAG
#define MROWS  768    // B*S
#define ENC_STRIDE (SDIM*DDIM)
#define MPB    (SDIM*SDIM)

// ---- scratch (device globals; no allocation allowed) ----
__device__ float g_enc[BDIM*SDIM*DDIM];
__device__ float g_Hh [BDIM*SDIM*K3];     // enc @ Wh + proj_b
__device__ float g_Ht [BDIM*SDIM*K3];     // enc @ Wt
__device__ float g_G  [BDIM*64];
__device__ float g_S  [BDIM*RSEQ*SDIM];
__device__ float g_Ws [BDIM*RSEQ*SDIM];
__device__ __align__(16) __nv_bfloat16 g_rwhi[NK*K3];        // relW^T hi, [n][k]
__device__ __align__(16) __nv_bfloat16 g_rwlo[NK*K3];        // relW^T lo
__device__ __align__(16) __nv_bfloat16 g_pwhi[2*K3*DDIM];    // proj_W^T hi, [z][n][k]
__device__ __align__(16) __nv_bfloat16 g_pwlo[2*K3*DDIM];    // proj_W^T lo

__device__ __forceinline__ uint32_t smem_u32(const void* p) {
    uint32_t a;
    asm("{ .reg .u64 t; cvta.to.shared.u64 t, %1; cvt.u32.u64 %0, t; }" : "=r"(a) : "l"(p));
    return a;
}
__device__ __forceinline__ void ldsm_x4(uint32_t* r, uint32_t addr) {
    asm volatile("ldmatrix.sync.aligned.m8n8.x4.shared.b16 {%0,%1,%2,%3}, [%4];"
        : "=r"(r[0]), "=r"(r[1]), "=r"(r[2]), "=r"(r[3]) : "r"(addr));
}
__device__ __forceinline__ void ldsm_x2(uint32_t* r, uint32_t addr) {
    asm volatile("ldmatrix.sync.aligned.m8n8.x2.shared.b16 {%0,%1}, [%2];"
        : "=r"(r[0]), "=r"(r[1]) : "r"(addr));
}
__device__ __forceinline__ void mma_bf16(float* d, const uint32_t* a, const uint32_t* b) {
    asm volatile("mma.sync.aligned.m16n8k16.row.col.f32.bf16.bf16.f32 "
        "{%0,%1,%2,%3}, {%4,%5,%6,%7}, {%8,%9}, {%0,%1,%2,%3};"
        : "+f"(d[0]), "+f"(d[1]), "+f"(d[2]), "+f"(d[3])
        : "r"(a[0]), "r"(a[1]), "r"(a[2]), "r"(a[3]), "r"(b[0]), "r"(b[1]));
}
// split fp32 pair -> bf16 hi2 + lo2
__device__ __forceinline__ void split2(float a0, float a1, uint32_t& hi, uint32_t& lo) {
    __nv_bfloat162 h2 = __float22bfloat162_rn(make_float2(a0, a1));
    float2 hf = __bfloat1622float2(h2);
    __nv_bfloat162 l2 = __float22bfloat162_rn(make_float2(a0 - hf.x, a1 - hf.y));
    hi = *(uint32_t*)&h2;
    lo = *(uint32_t*)&l2;
}

// ---------------------------------------------------------------------------
// refine phases (unchanged, passing)
// ---------------------------------------------------------------------------
__global__ __launch_bounds__(256, 1)
void refine_pre(const float* __restrict__ enc0, const float* __restrict__ rel) {
    const int part = blockIdx.x, b = blockIdx.y;
    const int tid = threadIdx.x, warp = tid >> 5, lane = tid & 31;
    __shared__ float sA[RSEQ*DDIM];
    const float scale = rsqrtf((float)DDIM);

    for (int i = tid; i < RSEQ*DDIM; i += 256) sA[i] = rel[b*RSEQ*DDIM + i];
    __syncthreads();

    if (part == 0) {
        int pair = tid >> 2, pt = tid & 3;
        int r = pair >> 3, q = pair & 7;
        float s = 0.f;
        for (int c = pt; c < DDIM; c += 4) s += sA[r*DDIM + c] * sA[q*DDIM + c];
        s += __shfl_down_sync(0xffffffffu, s, 2, 4);
        s += __shfl_down_sync(0xffffffffu, s, 1, 4);
        if (pt == 0) g_G[b*64 + pair] = s * scale;
    } else {
        int rowbase = (part - 1) * 16;
        for (int sl = warp; sl < 16; sl += 8) {
            int row = rowbase + sl;
            const float* erow = enc0 + (b*SDIM + row)*DDIM;
            float p[8];
            #pragma unroll
            for (int r = 0; r < 8; r++) p[r] = 0.f;
            for (int c = lane; c < DDIM; c += 32) {
                float e = erow[c];
                #pragma unroll
                for (int r = 0; r < 8; r++) p[r] += sA[r*DDIM + c] * e;
            }
            #pragma unroll
            for (int r = 0; r < 8; r++) {
                float v = p[r];
                #pragma unroll
                for (int o = 16; o > 0; o >>= 1) v += __shfl_down_sync(0xffffffffu, v, o);
                if (lane == 0) g_S[b*RSEQ*SDIM + r*SDIM + row] = v * scale;
            }
        }
    }
}

__global__ __launch_bounds__(256, 1)
void refine_scan() {
    const int b = blockIdx.x, tid = threadIdx.x, warp = tid >> 5, lane = tid & 31;
    __shared__ float sG[64], sS[RSEQ*SDIM], sW[RSEQ*SDIM], sWs[RSEQ*SDIM];
    if (tid < 64) sG[tid] = g_G[b*64 + tid];
    for (int i = tid; i < RSEQ*SDIM; i += 256) { sS[i] = g_S[b*RSEQ*SDIM + i]; sWs[i] = 0.f; }
    __syncthreads();

    for (int t = 0; t < RSTEPS; t++) {
        {
            const float* row = sS + warp*SDIM;
            float v0 = row[lane], v1 = row[lane+32], v2 = row[lane+64];
            float m = fmaxf(v0, fmaxf(v1, v2));
            #pragma unroll
            for (int o = 16; o > 0; o >>= 1) m = fmaxf(m, __shfl_xor_sync(0xffffffffu, m, o));
            float e0 = __expf(v0 - m), e1 = __expf(v1 - m), e2 = __expf(v2 - m);
            float sum = e0 + e1 + e2;
            #pragma unroll
            for (int o = 16; o > 0; o >>= 1) sum += __shfl_xor_sync(0xffffffffu, sum, o);
            float inv = 1.f / sum;
            sW [warp*SDIM + lane]    = e0*inv;
            sW [warp*SDIM + lane+32] = e1*inv;
            sW [warp*SDIM + lane+64] = e2*inv;
            sWs[warp*SDIM + lane]    += e0*inv;
            sWs[warp*SDIM + lane+32] += e1*inv;
            sWs[warp*SDIM + lane+64] += e2*inv;
        }
        __syncthreads();
        for (int idx = tid; idx < RSEQ*SDIM; idx += 256) {
            int r = idx / SDIM, s = idx - r*SDIM;
            float acc = sS[idx];
            #pragma unroll
            for (int q = 0; q < 8; q++) acc += sG[r*8 + q] * sW[q*SDIM + s];
            sS[idx] = acc;
        }
        __syncthreads();
    }
    for (int i = tid; i < RSEQ*SDIM; i += 256) g_Ws[b*RSEQ*SDIM + i] = sWs[i];
}

__global__ __launch_bounds__(256, 2)
void refine_post(const float* __restrict__ enc0, const float* __restrict__ rel) {
    const int b = blockIdx.y, s0 = blockIdx.x * 8;
    const int tid = threadIdx.x;
    __shared__ float sWs[8*8];
    __shared__ float sA[RSEQ*DDIM];
    if (tid < 64) {
        int sl = tid >> 3, r = tid & 7;
        sWs[sl*8 + r] = g_Ws[b*RSEQ*SDIM + r*SDIM + s0 + sl];
    }
    for (int i = tid; i < RSEQ*DDIM; i += 256) sA[i] = rel[b*RSEQ*DDIM + i];
    __syncthreads();
    for (int idx = tid; idx < 8*DDIM; idx += 256) {
        int sl = idx / DDIM, c = idx - sl*DDIM;
        int off = (b*SDIM + s0 + sl)*DDIM + c;
        float v = enc0[off];
        #pragma unroll
        for (int r = 0; r < 8; r++) v += sWs[sl*8 + r] * sA[r*DDIM + c];
        g_enc[off] = v;
    }
}

// ---------------------------------------------------------------------------
// prep: relW^T -> bf16 hi/lo [n][k]
// ---------------------------------------------------------------------------
__global__ __launch_bounds__(256, 4)
void prep_relw(const float* __restrict__ relW) {
    int idx = blockIdx.x * 256 + threadIdx.x;
    if (idx >= NK*K3) return;
    int n = idx / K3, k = idx - n*K3;
    float v = relW[(size_t)k*NK + n];
    __nv_bfloat16 hi = __float2bfloat16(v);
    __nv_bfloat16 lo = __float2bfloat16(v - __bfloat162float(hi));
    g_rwhi[idx] = hi;
    g_rwlo[idx] = lo;
}

// ---------------------------------------------------------------------------
// prep: proj_W^T -> bf16 hi/lo [z][n][k] via smem-tiled transpose.
// grid (K3/32, 1536/32), 256 threads
// ---------------------------------------------------------------------------
__global__ __launch_bounds__(256, 4)
void prep_projw(const float* __restrict__ pW) {
    __shared__ float tile[32][33];
    const int n0 = blockIdx.x*32, k0 = blockIdx.y*32;
    const int tid = threadIdx.x;
    const int z = k0 / DDIM, kz = k0 - z*DDIM;
    #pragma unroll
    for (int it = 0; it < 4; it++) {
        int r = (tid >> 5) + it*8, c = tid & 31;
        tile[r][c] = pW[(size_t)(k0 + r)*K3 + n0 + c];
    }
    __syncthreads();
    #pragma unroll
    for (int it = 0; it < 4; it++) {
        int n = (tid >> 5) + it*8, kk = tid & 31;
        float v = tile[kk][n];
        __nv_bfloat16 hi = __float2bfloat16(v);
        __nv_bfloat16 lo = __float2bfloat16(v - __bfloat162float(hi));
        size_t dst = (size_t)z*K3*DDIM + (size_t)(n0 + n)*DDIM + kz + kk;
        g_pwhi[dst] = hi;
        g_pwlo[dst] = lo;
    }
}

// ---------------------------------------------------------------------------
// hgemm via HMMA bf16 3-pass: O[z] = enc @ Wz (+pb for z=0)
// grid (K3/128, MROWS/128, 2), 256 threads = 8 warps (4 m x 2 n),
// CTA tile m128 x n128, K chunk 32.
// ---------------------------------------------------------------------------
#define ROWH 40   // smem row stride in halves (80B -> ldmatrix conflict-free)

__global__ __launch_bounds__(256, 2)
void hgemm_kernel(const float* __restrict__ pb) {
    __shared__ __align__(16) __nv_bfloat16 sAhi[128*ROWH], sAlo[128*ROWH];
    __shared__ __align__(16) __nv_bfloat16 sBhi[128*ROWH], sBlo[128*ROWH];

    const int tid = threadIdx.x, wid = tid >> 5, lane = tid & 31;
    const int n0 = blockIdx.x*128, m0 = blockIdx.y*128, z = blockIdx.z;
    const int wm = wid >> 1, wn = wid & 1;
    float* O = z ? g_Ht : g_Hh;
    const uint32_t* pwhiU = (const uint32_t*)(g_pwhi + (size_t)z*K3*DDIM);
    const uint32_t* pwloU = (const uint32_t*)(g_pwlo + (size_t)z*K3*DDIM);

    uint32_t* sAhiU = (uint32_t*)sAhi;
    uint32_t* sAloU = (uint32_t*)sAlo;
    uint32_t* sBhiU = (uint32_t*)sBhi;
    uint32_t* sBloU = (uint32_t*)sBlo;
    const uint32_t aHiBase = smem_u32(sAhi), aLoBase = smem_u32(sAlo);
    const uint32_t bHiBase = smem_u32(sBhi), bLoBase = smem_u32(sBlo);
    const uint32_t aRow = (uint32_t)(wm*32 + (lane & 15));
    const uint32_t aColH = (uint32_t)((lane >> 4) * 8);
    const uint32_t bRowL = (uint32_t)(lane & 7);
    const uint32_t bColH = (uint32_t)(((lane >> 3) & 1) * 8);

    float acc[2][8][4];
    #pragma unroll
    for (int t = 0; t < 2; t++)
        #pragma unroll
        for (int nt = 0; nt < 8; nt++)
            #pragma unroll
            for (int q = 0; q < 4; q++) acc[t][nt][q] = 0.f;

    for (int chunk = 0; chunk < DDIM/32; chunk++) {
        const int c0 = chunk*32;
        __syncthreads();
        #pragma unroll
        for (int it = 0; it < 8; it++) {
            int idx = tid + it*256;               // 128 rows x 16 u32
            int row = idx >> 4, cu = idx & 15;
            float2 e = *(const float2*)(g_enc + (size_t)(m0 + row)*DDIM + c0 + cu*2);
            uint32_t hi, lo;
            split2(e.x, e.y, hi, lo);
            uint32_t dst = (uint32_t)row*(ROWH/2) + cu;
            sAhiU[dst] = hi;
            sAloU[dst] = lo;
        }
        #pragma unroll
        for (int it = 0; it < 8; it++) {
            int idx = tid + it*256;               // 128 n x 16 u32
            int n = idx >> 4, cu = idx & 15;
            uint32_t src = (((uint32_t)(n0 + n)*DDIM + (uint32_t)c0) >> 1) + cu;
            uint32_t dst = (uint32_t)n*(ROWH/2) + cu;
            sBhiU[dst] = pwhiU[src];
            sBloU[dst] = pwloU[src];
        }
        __syncthreads();

        #pragma unroll
        for (int ks = 0; ks < 2; ks++) {
            uint32_t ahi[2][4], alo[2][4];
            #pragma unroll
            for (int t = 0; t < 2; t++) {
                uint32_t aoff = ((aRow + t*16)*ROWH + ks*16 + aColH) * 2;
                ldsm_x4(ahi[t], aHiBase + aoff);
                ldsm_x4(alo[t], aLoBase + aoff);
            }
            #pragma unroll
            for (int nt = 0; nt < 8; nt++) {
                uint32_t boff = (((uint32_t)(wn*64 + nt*8) + bRowL)*ROWH + ks*16 + bColH) * 2;
                uint32_t bhi[2], blo[2];
                ldsm_x2(bhi, bHiBase + boff);
                ldsm_x2(blo, bLoBase + boff);
                #pragma unroll
                for (int t = 0; t < 2; t++) {
                    mma_bf16(acc[t][nt], ahi[t], bhi);
                    mma_bf16(acc[t][nt], ahi[t], blo);
                    mma_bf16(acc[t][nt], alo[t], bhi);
                }
            }
        }
    }

    #pragma unroll
    for (int t = 0; t < 2; t++) {
        #pragma unroll
        for (int h = 0; h < 2; h++) {
            int row = m0 + wm*32 + t*16 + (lane >> 2) + h*8;
            #pragma unroll
            for (int nt = 0; nt < 8; nt++) {
                #pragma unroll
                for (int q = 0; q < 2; q++) {
                    int col = n0 + wn*64 + nt*8 + (lane & 3)*2 + q;
                    float v = acc[t][nt][h*2 + q];
                    if (z == 0) v += __ldg(pb + col);
                    O[(size_t)row*K3 + col] = v;
                }
            }
        }
    }
}

// ---------------------------------------------------------------------------
// pair GEMM via HMMA bf16 3-pass.
// CTA = 2 i-values x 96 j = 192 rows x N=72, K chunked by 32.
// One Ht load feeds both i rows -> 4x less L2 traffic than per-row build.
// 128 threads = 4 warps x 48 rows (3 m16-tiles). Static smem ~42.5 KB.
// ---------------------------------------------------------------------------
#define PROWS 192

__global__ __launch_bounds__(128, 2)
void pair_kernel(const float* __restrict__ relb, float* __restrict__ out) {
    __shared__ __align__(16) __nv_bfloat16 sAhi[PROWS*ROWH], sAlo[PROWS*ROWH];
    __shared__ __align__(16) __nv_bfloat16 sWhi[NK*ROWH],   sWlo[NK*ROWH];

    const int tid = threadIdx.x, wid = tid >> 5, lane = tid & 31;
    const int b  = blockIdx.x / (SDIM/2);          // 48 CTAs per batch
    const int i0 = (blockIdx.x - b*(SDIM/2)) * 2;

    const float* HtB  = g_Ht + (size_t)b*SDIM*K3;
    const float* Hh0  = g_Hh + (size_t)(b*SDIM + i0)*K3;
    const float* Hh1  = Hh0 + K3;

    uint32_t* sAhiU = (uint32_t*)sAhi;
    uint32_t* sAloU = (uint32_t*)sAlo;
    uint32_t* sWhiU = (uint32_t*)sWhi;
    uint32_t* sWloU = (uint32_t*)sWlo;
    const uint32_t* rwhiU = (const uint32_t*)g_rwhi;
    const uint32_t* rwloU = (const uint32_t*)g_rwlo;
    const uint32_t aHiBase = smem_u32(sAhi), aLoBase = smem_u32(sAlo);
    const uint32_t bHiBase = smem_u32(sWhi), bLoBase = smem_u32(sWlo);
    const uint32_t aRow = (uint32_t)(wid*48 + (lane & 15));
    const uint32_t aColH = (uint32_t)((lane >> 4) * 8);
    const uint32_t bRowL = (uint32_t)(lane & 7);
    const uint32_t bColH = (uint32_t)(((lane >> 3) & 1) * 8);

    float acc[3][9][4];
    #pragma unroll
    for (int t = 0; t < 3; t++)
        #pragma unroll
        for (int nt = 0; nt < 9; nt++)
            #pragma unroll
            for (int q = 0; q < 4; q++) acc[t][nt][q] = 0.f;

    for (int chunk = 0; chunk < K3/32; chunk++) {
        const int c0 = chunk*32;
        __syncthreads();

        // W chunk: 72 n x 16 u32 (hi,lo)
        #pragma unroll
        for (int it = 0; it < 9; it++) {
            int idx = tid + it*128;
            int n = idx >> 4, cu = idx & 15;
            uint32_t src = (((uint32_t)n*K3 + (uint32_t)c0) >> 1) + cu;
            uint32_t dst = (uint32_t)n*(ROWH/2) + cu;
            sWhiU[dst] = rwhiU[src];
            sWloU[dst] = rwloU[src];
        }
        // act chunk: one Ht[j] load builds rows j (ii=0) and 96+j (ii=1)
        #pragma unroll
        for (int it = 0; it < 12; it++) {
            int idx = tid + it*128;               // 96 j x 16 u32
            int j = idx >> 4, cu = idx & 15;
            int coff = c0 + cu*2;
            float2 ht = *(const float2*)(HtB + (size_t)j*K3 + coff);
            float2 h0 = *(const float2*)(Hh0 + coff);
            float2 h1 = *(const float2*)(Hh1 + coff);
            uint32_t hi, lo;
            uint32_t d0 = (uint32_t)j*(ROWH/2) + cu;
            split2(fmaxf(ht.x + h0.x, 0.f), fmaxf(ht.y + h0.y, 0.f), hi, lo);
            sAhiU[d0] = hi; sAloU[d0] = lo;
            uint32_t d1 = (uint32_t)(SDIM + j)*(ROWH/2) + cu;
            split2(fmaxf(ht.x + h1.x, 0.f), fmaxf(ht.y + h1.y, 0.f), hi, lo);
            sAhiU[d1] = hi; sAloU[d1] = lo;
        }
        __syncthreads();

        #pragma unroll
        for (int ks = 0; ks < 2; ks++) {
            uint32_t ahi[3][4], alo[3][4];
            #pragma unroll
            for (int t = 0; t < 3; t++) {
                uint32_t aoff = ((aRow + t*16)*ROWH + ks*16 + aColH) * 2;
                ldsm_x4(ahi[t], aHiBase + aoff);
                ldsm_x4(alo[t], aLoBase + aoff);
            }
            #pragma unroll
            for (int nt = 0; nt < 9; nt++) {
                uint32_t boff = (((uint32_t)(nt*8) + bRowL)*ROWH + ks*16 + bColH) * 2;
                uint32_t bhi[2], blo[2];
                ldsm_x2(bhi, bHiBase + boff);
                ldsm_x2(blo, bLoBase + boff);
                #pragma unroll
                for (int t = 0; t < 3; t++) {
                    mma_bf16(acc[t][nt], ahi[t], bhi);
                    mma_bf16(acc[t][nt], ahi[t], blo);
                    mma_bf16(acc[t][nt], alo[t], bhi);
                }
            }
        }
    }

    // epilogue: out[b][tag][r][i][j]
    #pragma unroll
    for (int t = 0; t < 3; t++) {
        #pragma unroll
        for (int h = 0; h < 2; h++) {
            int row = wid*48 + t*16 + (lane >> 2) + h*8;   // 0..191
            int ii = row / SDIM, j = row - ii*SDIM;
            int i = i0 + ii;
            #pragma unroll
            for (int nt = 0; nt < 9; nt++) {
                #pragma unroll
                for (int q = 0; q < 2; q++) {
                    int kk = nt*8 + (lane & 3)*2 + q;
                    int r = kk / TAGS, tg = kk - r*TAGS;
                    out[(((size_t)(b*TAGS + tg)*RSTEPS + r)*SDIM + i)*(size_t)SDIM + j]
                        = acc[t][nt][h*2 + q] + __ldg(relb + kk);
                }
            }
        }
    }
}

// ---------------------------------------------------------------------------
extern "C" void kernel_launch(void* const* d_in, const int* in_sizes, int n_in,
                              void* d_out, int out_size) {
    const float* enc0 = (const float*)d_in[0];
    const float* rel  = (const float*)d_in[1];
    const float* pW   = (const float*)d_in[2];
    const float* pb   = (const float*)d_in[3];
    const float* rW   = (const float*)d_in[4];
    const float* rb   = (const float*)d_in[5];
    float* out = (float*)d_out;

    refine_pre <<<dim3(7, BDIM), 256>>>(enc0, rel);
    refine_scan<<<BDIM, 256>>>();
    refine_post<<<dim3(12, BDIM), 256>>>(enc0, rel);
    prep_relw  <<<(NK*K3 + 255)/256, 256>>>(rW);
    prep_projw <<<dim3(K3/32, (2*DDIM)/32), 256>>>(pW);
    hgemm_kernel<<<dim3(K3/128, MROWS/128, 2), 256>>>(pb);
    pair_kernel<<<BDIM*(SDIM/2), 128>>>(rb, out);
}

// round 13
// speedup vs baseline: 3.8237x; 1.4504x over previous
#include <cuda_runtime.h>
#include <cuda_bf16.h>
#include <cuda_fp16.h>
#include <cstdint>

// Problem dims
#define BDIM   8
#define SDIM   96
#define DDIM   768
#define RSTEPS 24
#define RSEQ   8
#define TAGS   3
#define K3     2304   // 3*D
#define NK     72     // R*TAG
#define MROWS  768    // B*S
#define ENC_STRIDE (SDIM*DDIM)
#define MPB    (SDIM*SDIM)

// ---- scratch (device globals; no allocation allowed) ----
__device__ float g_enc[BDIM*SDIM*DDIM];
__device__ float g_Hh [BDIM*SDIM*K3];     // enc @ Wh + proj_b
__device__ float g_Ht [BDIM*SDIM*K3];     // enc @ Wt
__device__ float g_G  [BDIM*64];
__device__ float g_S  [BDIM*RSEQ*SDIM];
__device__ float g_Ws [BDIM*RSEQ*SDIM];
__device__ __align__(16) __half g_rwhi[NK*K3];               // relW^T hi (fp16), [n][k]
__device__ __align__(16) __half g_rwlo[NK*K3];               // relW^T lo (fp16)
__device__ __align__(16) __nv_bfloat16 g_pwhi[2*K3*DDIM];    // proj_W^T hi (bf16), [z][n][k]
__device__ __align__(16) __nv_bfloat16 g_pwlo[2*K3*DDIM];    // proj_W^T lo

__device__ __forceinline__ uint32_t smem_u32(const void* p) {
    uint32_t a;
    asm("{ .reg .u64 t; cvta.to.shared.u64 t, %1; cvt.u32.u64 %0, t; }" : "=r"(a) : "l"(p));
    return a;
}
__device__ __forceinline__ void ldsm_x4(uint32_t* r, uint32_t addr) {
    asm volatile("ldmatrix.sync.aligned.m8n8.x4.shared.b16 {%0,%1,%2,%3}, [%4];"
        : "=r"(r[0]), "=r"(r[1]), "=r"(r[2]), "=r"(r[3]) : "r"(addr));
}
__device__ __forceinline__ void ldsm_x2(uint32_t* r, uint32_t addr) {
    asm volatile("ldmatrix.sync.aligned.m8n8.x2.shared.b16 {%0,%1}, [%2];"
        : "=r"(r[0]), "=r"(r[1]) : "r"(addr));
}
__device__ __forceinline__ void mma_bf16(float* d, const uint32_t* a, const uint32_t* b) {
    asm volatile("mma.sync.aligned.m16n8k16.row.col.f32.bf16.bf16.f32 "
        "{%0,%1,%2,%3}, {%4,%5,%6,%7}, {%8,%9}, {%0,%1,%2,%3};"
        : "+f"(d[0]), "+f"(d[1]), "+f"(d[2]), "+f"(d[3])
        : "r"(a[0]), "r"(a[1]), "r"(a[2]), "r"(a[3]), "r"(b[0]), "r"(b[1]));
}
__device__ __forceinline__ void mma_fp16(float* d, const uint32_t* a, const uint32_t* b) {
    asm volatile("mma.sync.aligned.m16n8k16.row.col.f32.f16.f16.f32 "
        "{%0,%1,%2,%3}, {%4,%5,%6,%7}, {%8,%9}, {%0,%1,%2,%3};"
        : "+f"(d[0]), "+f"(d[1]), "+f"(d[2]), "+f"(d[3])
        : "r"(a[0]), "r"(a[1]), "r"(a[2]), "r"(a[3]), "r"(b[0]), "r"(b[1]));
}
// split fp32 pair -> bf16 hi2 + lo2
__device__ __forceinline__ void split2(float a0, float a1, uint32_t& hi, uint32_t& lo) {
    __nv_bfloat162 h2 = __float22bfloat162_rn(make_float2(a0, a1));
    float2 hf = __bfloat1622float2(h2);
    __nv_bfloat162 l2 = __float22bfloat162_rn(make_float2(a0 - hf.x, a1 - hf.y));
    hi = *(uint32_t*)&h2;
    lo = *(uint32_t*)&l2;
}

// ---------------------------------------------------------------------------
// refine, phase 1  (proven)
// ---------------------------------------------------------------------------
__global__ __launch_bounds__(256, 1)
void refine_pre(const float* __restrict__ enc0, const float* __restrict__ rel) {
    const int part = blockIdx.x, b = blockIdx.y;
    const int tid = threadIdx.x, warp = tid >> 5, lane = tid & 31;
    __shared__ float sA[RSEQ*DDIM];
    const float scale = rsqrtf((float)DDIM);

    for (int i = tid; i < RSEQ*DDIM; i += 256) sA[i] = rel[b*RSEQ*DDIM + i];
    __syncthreads();

    if (part == 0) {
        int pair = tid >> 2, pt = tid & 3;
        int r = pair >> 3, q = pair & 7;
        float s = 0.f;
        for (int c = pt; c < DDIM; c += 4) s += sA[r*DDIM + c] * sA[q*DDIM + c];
        s += __shfl_down_sync(0xffffffffu, s, 2, 4);
        s += __shfl_down_sync(0xffffffffu, s, 1, 4);
        if (pt == 0) g_G[b*64 + pair] = s * scale;
    } else {
        int rowbase = (part - 1) * 16;
        for (int sl = warp; sl < 16; sl += 8) {
            int row = rowbase + sl;
            const float* erow = enc0 + (b*SDIM + row)*DDIM;
            float p[8];
            #pragma unroll
            for (int r = 0; r < 8; r++) p[r] = 0.f;
            for (int c = lane; c < DDIM; c += 32) {
                float e = erow[c];
                #pragma unroll
                for (int r = 0; r < 8; r++) p[r] += sA[r*DDIM + c] * e;
            }
            #pragma unroll
            for (int r = 0; r < 8; r++) {
                float v = p[r];
                #pragma unroll
                for (int o = 16; o > 0; o >>= 1) v += __shfl_down_sync(0xffffffffu, v, o);
                if (lane == 0) g_S[b*RSEQ*SDIM + r*SDIM + row] = v * scale;
            }
        }
    }
}

// ---------------------------------------------------------------------------
// refine, phase 2  (proven)
// ---------------------------------------------------------------------------
__global__ __launch_bounds__(256, 1)
void refine_scan() {
    const int b = blockIdx.x, tid = threadIdx.x, warp = tid >> 5, lane = tid & 31;
    __shared__ float sG[64], sS[RSEQ*SDIM], sW[RSEQ*SDIM], sWs[RSEQ*SDIM];
    if (tid < 64) sG[tid] = g_G[b*64 + tid];
    for (int i = tid; i < RSEQ*SDIM; i += 256) { sS[i] = g_S[b*RSEQ*SDIM + i]; sWs[i] = 0.f; }
    __syncthreads();

    for (int t = 0; t < RSTEPS; t++) {
        {
            const float* row = sS + warp*SDIM;
            float v0 = row[lane], v1 = row[lane+32], v2 = row[lane+64];
            float m = fmaxf(v0, fmaxf(v1, v2));
            #pragma unroll
            for (int o = 16; o > 0; o >>= 1) m = fmaxf(m, __shfl_xor_sync(0xffffffffu, m, o));
            float e0 = __expf(v0 - m), e1 = __expf(v1 - m), e2 = __expf(v2 - m);
            float sum = e0 + e1 + e2;
            #pragma unroll
            for (int o = 16; o > 0; o >>= 1) sum += __shfl_xor_sync(0xffffffffu, sum, o);
            float inv = 1.f / sum;
            sW [warp*SDIM + lane]    = e0*inv;
            sW [warp*SDIM + lane+32] = e1*inv;
            sW [warp*SDIM + lane+64] = e2*inv;
            sWs[warp*SDIM + lane]    += e0*inv;
            sWs[warp*SDIM + lane+32] += e1*inv;
            sWs[warp*SDIM + lane+64] += e2*inv;
        }
        __syncthreads();
        for (int idx = tid; idx < RSEQ*SDIM; idx += 256) {
            int r = idx / SDIM, s = idx - r*SDIM;
            float acc = sS[idx];
            #pragma unroll
            for (int q = 0; q < 8; q++) acc += sG[r*8 + q] * sW[q*SDIM + s];
            sS[idx] = acc;
        }
        __syncthreads();
    }
    for (int i = tid; i < RSEQ*SDIM; i += 256) g_Ws[b*RSEQ*SDIM + i] = sWs[i];
}

// ---------------------------------------------------------------------------
// refine, phase 3  (proven)
// ---------------------------------------------------------------------------
__global__ __launch_bounds__(256, 2)
void refine_post(const float* __restrict__ enc0, const float* __restrict__ rel) {
    const int b = blockIdx.y, s0 = blockIdx.x * 8;
    const int tid = threadIdx.x;
    __shared__ float sWs[8*8];
    __shared__ float sA[RSEQ*DDIM];
    if (tid < 64) {
        int sl = tid >> 3, r = tid & 7;
        sWs[sl*8 + r] = g_Ws[b*RSEQ*SDIM + r*SDIM + s0 + sl];
    }
    for (int i = tid; i < RSEQ*DDIM; i += 256) sA[i] = rel[b*RSEQ*DDIM + i];
    __syncthreads();
    for (int idx = tid; idx < 8*DDIM; idx += 256) {
        int sl = idx / DDIM, c = idx - sl*DDIM;
        int off = (b*SDIM + s0 + sl)*DDIM + c;
        float v = enc0[off];
        #pragma unroll
        for (int r = 0; r < 8; r++) v += sWs[sl*8 + r] * sA[r*DDIM + c];
        g_enc[off] = v;
    }
}

// ---------------------------------------------------------------------------
// prep: relW^T -> fp16 hi/lo [n][k]   (type changed bf16 -> fp16)
// ---------------------------------------------------------------------------
__global__ __launch_bounds__(256, 4)
void prep_relw(const float* __restrict__ relW) {
    int idx = blockIdx.x * 256 + threadIdx.x;
    if (idx >= NK*K3) return;
    int n = idx / K3, k = idx - n*K3;
    float v = relW[(size_t)k*NK + n];
    __half hi = __float2half_rn(v);
    __half lo = __float2half_rn(v - __half2float(hi));
    g_rwhi[idx] = hi;
    g_rwlo[idx] = lo;
}

// ---------------------------------------------------------------------------
// prep: proj_W^T -> bf16 hi/lo [z][n][k]  (proven)
// ---------------------------------------------------------------------------
__global__ __launch_bounds__(256, 4)
void prep_projw(const float* __restrict__ pW) {
    __shared__ float tile[32][33];
    const int n0 = blockIdx.x*32, k0 = blockIdx.y*32;
    const int tid = threadIdx.x;
    const int z = k0 / DDIM, kz = k0 - z*DDIM;
    #pragma unroll
    for (int it = 0; it < 4; it++) {
        int r = (tid >> 5) + it*8, c = tid & 31;
        tile[r][c] = pW[(size_t)(k0 + r)*K3 + n0 + c];
    }
    __syncthreads();
    #pragma unroll
    for (int it = 0; it < 4; it++) {
        int n = (tid >> 5) + it*8, kk = tid & 31;
        float v = tile[kk][n];
        __nv_bfloat16 hi = __float2bfloat16(v);
        __nv_bfloat16 lo = __float2bfloat16(v - __bfloat162float(hi));
        size_t dst = (size_t)z*K3*DDIM + (size_t)(n0 + n)*DDIM + kz + kk;
        g_pwhi[dst] = hi;
        g_pwlo[dst] = lo;
    }
}

// ---------------------------------------------------------------------------
// hgemm via HMMA bf16 3-pass  (proven, unchanged)
// ---------------------------------------------------------------------------
#define ROWH 40   // smem row stride in halves (80B -> ldmatrix conflict-free)

__global__ __launch_bounds__(256, 2)
void hgemm_kernel(const float* __restrict__ pb) {
    __shared__ __align__(16) __nv_bfloat16 sAhi[128*ROWH], sAlo[128*ROWH];
    __shared__ __align__(16) __nv_bfloat16 sBhi[128*ROWH], sBlo[128*ROWH];

    const int tid = threadIdx.x, wid = tid >> 5, lane = tid & 31;
    const int n0 = blockIdx.x*128, m0 = blockIdx.y*128, z = blockIdx.z;
    const int wm = wid >> 1, wn = wid & 1;
    float* O = z ? g_Ht : g_Hh;
    const uint32_t* pwhiU = (const uint32_t*)(g_pwhi + (size_t)z*K3*DDIM);
    const uint32_t* pwloU = (const uint32_t*)(g_pwlo + (size_t)z*K3*DDIM);

    uint32_t* sAhiU = (uint32_t*)sAhi;
    uint32_t* sAloU = (uint32_t*)sAlo;
    uint32_t* sBhiU = (uint32_t*)sBhi;
    uint32_t* sBloU = (uint32_t*)sBlo;
    const uint32_t aHiBase = smem_u32(sAhi), aLoBase = smem_u32(sAlo);
    const uint32_t bHiBase = smem_u32(sBhi), bLoBase = smem_u32(sBlo);
    const uint32_t aRow = (uint32_t)(wm*32 + (lane & 15));
    const uint32_t aColH = (uint32_t)((lane >> 4) * 8);
    const uint32_t bRowL = (uint32_t)(lane & 7);
    const uint32_t bColH = (uint32_t)(((lane >> 3) & 1) * 8);

    float acc[2][8][4];
    #pragma unroll
    for (int t = 0; t < 2; t++)
        #pragma unroll
        for (int nt = 0; nt < 8; nt++)
            #pragma unroll
            for (int q = 0; q < 4; q++) acc[t][nt][q] = 0.f;

    for (int chunk = 0; chunk < DDIM/32; chunk++) {
        const int c0 = chunk*32;
        __syncthreads();
        #pragma unroll
        for (int it = 0; it < 8; it++) {
            int idx = tid + it*256;               // 128 rows x 16 u32
            int row = idx >> 4, cu = idx & 15;
            float2 e = *(const float2*)(g_enc + (size_t)(m0 + row)*DDIM + c0 + cu*2);
            uint32_t hi, lo;
            split2(e.x, e.y, hi, lo);
            uint32_t dst = (uint32_t)row*(ROWH/2) + cu;
            sAhiU[dst] = hi;
            sAloU[dst] = lo;
        }
        #pragma unroll
        for (int it = 0; it < 8; it++) {
            int idx = tid + it*256;               // 128 n x 16 u32
            int n = idx >> 4, cu = idx & 15;
            uint32_t src = (((uint32_t)(n0 + n)*DDIM + (uint32_t)c0) >> 1) + cu;
            uint32_t dst = (uint32_t)n*(ROWH/2) + cu;
            sBhiU[dst] = pwhiU[src];
            sBloU[dst] = pwloU[src];
        }
        __syncthreads();

        #pragma unroll
        for (int ks = 0; ks < 2; ks++) {
            uint32_t ahi[2][4], alo[2][4];
            #pragma unroll
            for (int t = 0; t < 2; t++) {
                uint32_t aoff = ((aRow + t*16)*ROWH + ks*16 + aColH) * 2;
                ldsm_x4(ahi[t], aHiBase + aoff);
                ldsm_x4(alo[t], aLoBase + aoff);
            }
            #pragma unroll
            for (int nt = 0; nt < 8; nt++) {
                uint32_t boff = (((uint32_t)(wn*64 + nt*8) + bRowL)*ROWH + ks*16 + bColH) * 2;
                uint32_t bhi[2], blo[2];
                ldsm_x2(bhi, bHiBase + boff);
                ldsm_x2(blo, bLoBase + boff);
                #pragma unroll
                for (int t = 0; t < 2; t++) {
                    mma_bf16(acc[t][nt], ahi[t], bhi);
                    mma_bf16(acc[t][nt], ahi[t], blo);
                    mma_bf16(acc[t][nt], alo[t], bhi);
                }
            }
        }
    }

    #pragma unroll
    for (int t = 0; t < 2; t++) {
        #pragma unroll
        for (int h = 0; h < 2; h++) {
            int row = m0 + wm*32 + t*16 + (lane >> 2) + h*8;
            #pragma unroll
            for (int nt = 0; nt < 8; nt++) {
                #pragma unroll
                for (int q = 0; q < 2; q++) {
                    int col = n0 + wn*64 + nt*8 + (lane & 3)*2 + q;
                    float v = acc[t][nt][h*2 + q];
                    if (z == 0) v += __ldg(pb + col);
                    O[(size_t)row*K3 + col] = v;
                }
            }
        }
    }
}

// ---------------------------------------------------------------------------
// pair GEMM via HMMA fp16 2-pass: D = act_fp16 * (Whi + Wlo)
// act single fp16 (residual 2^-12 rel, only dropped term); relW exact as hi+lo.
// CTA = 2 i x 96 j = 192 rows x N=72, K chunk 32, 128 threads, 3 CTAs/SM.
// B hi+lo fetched with ONE dual-buffer ldmatrix.x4 (lanes 0-15 hi, 16-31 lo).
// ---------------------------------------------------------------------------
#define PROWS 192

__global__ __launch_bounds__(128, 3)
void pair_kernel(const float* __restrict__ relb, float* __restrict__ out) {
    __shared__ __align__(16) __half sA[PROWS*ROWH];      // 15360 B
    __shared__ __align__(16) __half sW[2][NK*ROWH];      // hi | lo contiguous, 5760 B each

    const int tid = threadIdx.x, wid = tid >> 5, lane = tid & 31;
    const int b  = blockIdx.x / (SDIM/2);          // 48 CTAs per batch
    const int i0 = (blockIdx.x - b*(SDIM/2)) * 2;

    const float* HtB  = g_Ht + (size_t)b*SDIM*K3;
    const float* Hh0  = g_Hh + (size_t)(b*SDIM + i0)*K3;
    const float* Hh1  = Hh0 + K3;

    uint32_t* sAU  = (uint32_t*)sA;
    uint32_t* sWhiU = (uint32_t*)sW[0];
    uint32_t* sWloU = (uint32_t*)sW[1];
    const uint32_t* rwhiU = (const uint32_t*)g_rwhi;
    const uint32_t* rwloU = (const uint32_t*)g_rwlo;
    const uint32_t aBase = smem_u32(sA);
    const uint32_t bBase = smem_u32(sW[0]);

    const uint32_t aRow  = (uint32_t)(wid*48 + (lane & 15));
    const uint32_t aColH = (uint32_t)((lane >> 4) * 8);
    // B dual-buffer x4: lanes 0-15 use hi buffer, 16-31 the lo buffer (same pattern)
    const int l16 = lane & 15;
    const uint32_t bSel  = (lane >= 16) ? (uint32_t)(NK*ROWH*2) : 0u;   // byte offset of sW[1]
    const uint32_t bRowL = (uint32_t)(l16 & 7);
    const uint32_t bColH = (uint32_t)(((l16 >> 3) & 1) * 8);

    float acc[3][9][4];
    #pragma unroll
    for (int t = 0; t < 3; t++)
        #pragma unroll
        for (int nt = 0; nt < 9; nt++)
            #pragma unroll
            for (int q = 0; q < 4; q++) acc[t][nt][q] = 0.f;

    for (int chunk = 0; chunk < K3/32; chunk++) {
        const int c0 = chunk*32;
        __syncthreads();

        // W chunk: 72 n x 16 u32 per buffer
        #pragma unroll
        for (int it = 0; it < 9; it++) {
            int idx = tid + it*128;
            int n = idx >> 4, cu = idx & 15;
            uint32_t src = (((uint32_t)n*K3 + (uint32_t)c0) >> 1) + cu;
            uint32_t dst = (uint32_t)n*(ROWH/2) + cu;
            sWhiU[dst] = rwhiU[src];
            sWloU[dst] = rwloU[src];
        }
        // act chunk: single fp16, one Ht[j] load feeds rows j and 96+j
        #pragma unroll
        for (int it = 0; it < 12; it++) {
            int idx = tid + it*128;               // 96 j x 16 u32
            int j = idx >> 4, cu = idx & 15;
            int coff = c0 + cu*2;
            float2 ht = *(const float2*)(HtB + (size_t)j*K3 + coff);
            float2 h0 = *(const float2*)(Hh0 + coff);
            float2 h1 = *(const float2*)(Hh1 + coff);
            __half2 v0 = __float22half2_rn(make_float2(fmaxf(ht.x + h0.x, 0.f),
                                                       fmaxf(ht.y + h0.y, 0.f)));
            __half2 v1 = __float22half2_rn(make_float2(fmaxf(ht.x + h1.x, 0.f),
                                                       fmaxf(ht.y + h1.y, 0.f)));
            sAU[(uint32_t)j*(ROWH/2) + cu]          = *(uint32_t*)&v0;
            sAU[(uint32_t)(SDIM + j)*(ROWH/2) + cu] = *(uint32_t*)&v1;
        }
        __syncthreads();

        #pragma unroll
        for (int ks = 0; ks < 2; ks++) {
            uint32_t a[3][4];
            #pragma unroll
            for (int t = 0; t < 3; t++) {
                uint32_t aoff = ((aRow + t*16)*ROWH + ks*16 + aColH) * 2;
                ldsm_x4(a[t], aBase + aoff);
            }
            #pragma unroll
            for (int nt = 0; nt < 9; nt++) {
                uint32_t boff = (((uint32_t)(nt*8) + bRowL)*ROWH + ks*16 + bColH) * 2;
                uint32_t bb[4];                    // bb[0..1]=Whi frag, bb[2..3]=Wlo frag
                ldsm_x4(bb, bBase + bSel + boff);
                #pragma unroll
                for (int t = 0; t < 3; t++) {
                    mma_fp16(acc[t][nt], a[t], bb);      // A * Whi
                    mma_fp16(acc[t][nt], a[t], bb + 2);  // A * Wlo
                }
            }
        }
    }

    // epilogue: out[b][tag][r][i][j]
    #pragma unroll
    for (int t = 0; t < 3; t++) {
        #pragma unroll
        for (int h = 0; h < 2; h++) {
            int row = wid*48 + t*16 + (lane >> 2) + h*8;   // 0..191
            int ii = row / SDIM, j = row - ii*SDIM;
            int i = i0 + ii;
            #pragma unroll
            for (int nt = 0; nt < 9; nt++) {
                #pragma unroll
                for (int q = 0; q < 2; q++) {
                    int kk = nt*8 + (lane & 3)*2 + q;
                    int r = kk / TAGS, tg = kk - r*TAGS;
                    out[(((size_t)(b*TAGS + tg)*RSTEPS + r)*SDIM + i)*(size_t)SDIM + j]
                        = acc[t][nt][h*2 + q] + __ldg(relb + kk);
                }
            }
        }
    }
}

// ---------------------------------------------------------------------------
extern "C" void kernel_launch(void* const* d_in, const int* in_sizes, int n_in,
                              void* d_out, int out_size) {
    const float* enc0 = (const float*)d_in[0];
    const float* rel  = (const float*)d_in[1];
    const float* pW   = (const float*)d_in[2];
    const float* pb   = (const float*)d_in[3];
    const float* rW   = (const float*)d_in[4];
    const float* rb   = (const float*)d_in[5];
    float* out = (float*)d_out;

    refine_pre <<<dim3(7, BDIM), 256>>>(enc0, rel);
    refine_scan<<<BDIM, 256>>>();
    refine_post<<<dim3(12, BDIM), 256>>>(enc0, rel);
    prep_relw  <<<(NK*K3 + 255)/256, 256>>>(rW);
    prep_projw <<<dim3(K3/32, (2*DDIM)/32), 256>>>(pW);
    hgemm_kernel<<<dim3(K3/128, MROWS/128, 2), 256>>>(pb);
    pair_kernel<<<BDIM*(SDIM/2), 128>>>(rb, out);
}

// round 14
// speedup vs baseline: 5.1976x; 1.3593x over previous
#include <cuda_runtime.h>
#include <cuda_bf16.h>
#include <cuda_fp16.h>
#include <cstdint>

// Problem dims
#define BDIM   8
#define SDIM   96
#define DDIM   768
#define RSTEPS 24
#define RSEQ   8
#define TAGS   3
#define K3     2304   // 3*D
#define NK     72     // R*TAG
#define MROWS  768    // B*S
#define ENC_STRIDE (SDIM*DDIM)
#define MPB    (SDIM*SDIM)

// ---- scratch (device globals; no allocation allowed) ----
__device__ float g_enc[BDIM*SDIM*DDIM];
__device__ float g_Hh [BDIM*SDIM*K3];     // enc @ Wh + proj_b
__device__ float g_Ht [BDIM*SDIM*K3];     // enc @ Wt
__device__ float g_G  [BDIM*64];
__device__ float g_S  [BDIM*RSEQ*SDIM];
__device__ float g_Ws [BDIM*RSEQ*SDIM];
__device__ __align__(16) __half g_rwhi[NK*K3];               // relW^T (fp16), [n][k]
__device__ __align__(16) __nv_bfloat16 g_pwhi[2*K3*DDIM];    // proj_W^T hi (bf16), [z][n][k]
__device__ __align__(16) __nv_bfloat16 g_pwlo[2*K3*DDIM];    // proj_W^T lo

__device__ __forceinline__ uint32_t smem_u32(const void* p) {
    uint32_t a;
    asm("{ .reg .u64 t; cvta.to.shared.u64 t, %1; cvt.u32.u64 %0, t; }" : "=r"(a) : "l"(p));
    return a;
}
__device__ __forceinline__ void ldsm_x4(uint32_t* r, uint32_t addr) {
    asm volatile("ldmatrix.sync.aligned.m8n8.x4.shared.b16 {%0,%1,%2,%3}, [%4];"
        : "=r"(r[0]), "=r"(r[1]), "=r"(r[2]), "=r"(r[3]) : "r"(addr));
}
__device__ __forceinline__ void ldsm_x2(uint32_t* r, uint32_t addr) {
    asm volatile("ldmatrix.sync.aligned.m8n8.x2.shared.b16 {%0,%1}, [%2];"
        : "=r"(r[0]), "=r"(r[1]) : "r"(addr));
}
__device__ __forceinline__ void mma_bf16(float* d, const uint32_t* a, const uint32_t* b) {
    asm volatile("mma.sync.aligned.m16n8k16.row.col.f32.bf16.bf16.f32 "
        "{%0,%1,%2,%3}, {%4,%5,%6,%7}, {%8,%9}, {%0,%1,%2,%3};"
        : "+f"(d[0]), "+f"(d[1]), "+f"(d[2]), "+f"(d[3])
        : "r"(a[0]), "r"(a[1]), "r"(a[2]), "r"(a[3]), "r"(b[0]), "r"(b[1]));
}
__device__ __forceinline__ void mma_fp16(float* d, const uint32_t* a, const uint32_t* b) {
    asm volatile("mma.sync.aligned.m16n8k16.row.col.f32.f16.f16.f32 "
        "{%0,%1,%2,%3}, {%4,%5,%6,%7}, {%8,%9}, {%0,%1,%2,%3};"
        : "+f"(d[0]), "+f"(d[1]), "+f"(d[2]), "+f"(d[3])
        : "r"(a[0]), "r"(a[1]), "r"(a[2]), "r"(a[3]), "r"(b[0]), "r"(b[1]));
}
// split fp32 pair -> bf16 hi2 + lo2
__device__ __forceinline__ void split2(float a0, float a1, uint32_t& hi, uint32_t& lo) {
    __nv_bfloat162 h2 = __float22bfloat162_rn(make_float2(a0, a1));
    float2 hf = __bfloat1622float2(h2);
    __nv_bfloat162 l2 = __float22bfloat162_rn(make_float2(a0 - hf.x, a1 - hf.y));
    hi = *(uint32_t*)&h2;
    lo = *(uint32_t*)&l2;
}

// ---------------------------------------------------------------------------
// refine, phase 1  (proven)
// ---------------------------------------------------------------------------
__global__ __launch_bounds__(256, 1)
void refine_pre(const float* __restrict__ enc0, const float* __restrict__ rel) {
    const int part = blockIdx.x, b = blockIdx.y;
    const int tid = threadIdx.x, warp = tid >> 5, lane = tid & 31;
    __shared__ float sA[RSEQ*DDIM];
    const float scale = rsqrtf((float)DDIM);

    for (int i = tid; i < RSEQ*DDIM; i += 256) sA[i] = rel[b*RSEQ*DDIM + i];
    __syncthreads();

    if (part == 0) {
        int pair = tid >> 2, pt = tid & 3;
        int r = pair >> 3, q = pair & 7;
        float s = 0.f;
        for (int c = pt; c < DDIM; c += 4) s += sA[r*DDIM + c] * sA[q*DDIM + c];
        s += __shfl_down_sync(0xffffffffu, s, 2, 4);
        s += __shfl_down_sync(0xffffffffu, s, 1, 4);
        if (pt == 0) g_G[b*64 + pair] = s * scale;
    } else {
        int rowbase = (part - 1) * 16;
        for (int sl = warp; sl < 16; sl += 8) {
            int row = rowbase + sl;
            const float* erow = enc0 + (b*SDIM + row)*DDIM;
            float p[8];
            #pragma unroll
            for (int r = 0; r < 8; r++) p[r] = 0.f;
            for (int c = lane; c < DDIM; c += 32) {
                float e = erow[c];
                #pragma unroll
                for (int r = 0; r < 8; r++) p[r] += sA[r*DDIM + c] * e;
            }
            #pragma unroll
            for (int r = 0; r < 8; r++) {
                float v = p[r];
                #pragma unroll
                for (int o = 16; o > 0; o >>= 1) v += __shfl_down_sync(0xffffffffu, v, o);
                if (lane == 0) g_S[b*RSEQ*SDIM + r*SDIM + row] = v * scale;
            }
        }
    }
}

// ---------------------------------------------------------------------------
// refine, phase 2  (proven)
// ---------------------------------------------------------------------------
__global__ __launch_bounds__(256, 1)
void refine_scan() {
    const int b = blockIdx.x, tid = threadIdx.x, warp = tid >> 5, lane = tid & 31;
    __shared__ float sG[64], sS[RSEQ*SDIM], sW[RSEQ*SDIM], sWs[RSEQ*SDIM];
    if (tid < 64) sG[tid] = g_G[b*64 + tid];
    for (int i = tid; i < RSEQ*SDIM; i += 256) { sS[i] = g_S[b*RSEQ*SDIM + i]; sWs[i] = 0.f; }
    __syncthreads();

    for (int t = 0; t < RSTEPS; t++) {
        {
            const float* row = sS + warp*SDIM;
            float v0 = row[lane], v1 = row[lane+32], v2 = row[lane+64];
            float m = fmaxf(v0, fmaxf(v1, v2));
            #pragma unroll
            for (int o = 16; o > 0; o >>= 1) m = fmaxf(m, __shfl_xor_sync(0xffffffffu, m, o));
            float e0 = __expf(v0 - m), e1 = __expf(v1 - m), e2 = __expf(v2 - m);
            float sum = e0 + e1 + e2;
            #pragma unroll
            for (int o = 16; o > 0; o >>= 1) sum += __shfl_xor_sync(0xffffffffu, sum, o);
            float inv = 1.f / sum;
            sW [warp*SDIM + lane]    = e0*inv;
            sW [warp*SDIM + lane+32] = e1*inv;
            sW [warp*SDIM + lane+64] = e2*inv;
            sWs[warp*SDIM + lane]    += e0*inv;
            sWs[warp*SDIM + lane+32] += e1*inv;
            sWs[warp*SDIM + lane+64] += e2*inv;
        }
        __syncthreads();
        for (int idx = tid; idx < RSEQ*SDIM; idx += 256) {
            int r = idx / SDIM, s = idx - r*SDIM;
            float acc = sS[idx];
            #pragma unroll
            for (int q = 0; q < 8; q++) acc += sG[r*8 + q] * sW[q*SDIM + s];
            sS[idx] = acc;
        }
        __syncthreads();
    }
    for (int i = tid; i < RSEQ*SDIM; i += 256) g_Ws[b*RSEQ*SDIM + i] = sWs[i];
}

// ---------------------------------------------------------------------------
// refine, phase 3  (proven)
// ---------------------------------------------------------------------------
__global__ __launch_bounds__(256, 2)
void refine_post(const float* __restrict__ enc0, const float* __restrict__ rel) {
    const int b = blockIdx.y, s0 = blockIdx.x * 8;
    const int tid = threadIdx.x;
    __shared__ float sWs[8*8];
    __shared__ float sA[RSEQ*DDIM];
    if (tid < 64) {
        int sl = tid >> 3, r = tid & 7;
        sWs[sl*8 + r] = g_Ws[b*RSEQ*SDIM + r*SDIM + s0 + sl];
    }
    for (int i = tid; i < RSEQ*DDIM; i += 256) sA[i] = rel[b*RSEQ*DDIM + i];
    __syncthreads();
    for (int idx = tid; idx < 8*DDIM; idx += 256) {
        int sl = idx / DDIM, c = idx - sl*DDIM;
        int off = (b*SDIM + s0 + sl)*DDIM + c;
        float v = enc0[off];
        #pragma unroll
        for (int r = 0; r < 8; r++) v += sWs[sl*8 + r] * sA[r*DDIM + c];
        g_enc[off] = v;
    }
}

// ---------------------------------------------------------------------------
// prep: relW^T -> single fp16 [n][k]
// ---------------------------------------------------------------------------
__global__ __launch_bounds__(256, 4)
void prep_relw(const float* __restrict__ relW) {
    int idx = blockIdx.x * 256 + threadIdx.x;
    if (idx >= NK*K3) return;
    int n = idx / K3, k = idx - n*K3;
    g_rwhi[idx] = __float2half_rn(relW[(size_t)k*NK + n]);
}

// ---------------------------------------------------------------------------
// prep: proj_W^T -> bf16 hi/lo [z][n][k]  (proven)
// ---------------------------------------------------------------------------
__global__ __launch_bounds__(256, 4)
void prep_projw(const float* __restrict__ pW) {
    __shared__ float tile[32][33];
    const int n0 = blockIdx.x*32, k0 = blockIdx.y*32;
    const int tid = threadIdx.x;
    const int z = k0 / DDIM, kz = k0 - z*DDIM;
    #pragma unroll
    for (int it = 0; it < 4; it++) {
        int r = (tid >> 5) + it*8, c = tid & 31;
        tile[r][c] = pW[(size_t)(k0 + r)*K3 + n0 + c];
    }
    __syncthreads();
    #pragma unroll
    for (int it = 0; it < 4; it++) {
        int n = (tid >> 5) + it*8, kk = tid & 31;
        float v = tile[kk][n];
        __nv_bfloat16 hi = __float2bfloat16(v);
        __nv_bfloat16 lo = __float2bfloat16(v - __bfloat162float(hi));
        size_t dst = (size_t)z*K3*DDIM + (size_t)(n0 + n)*DDIM + kz + kk;
        g_pwhi[dst] = hi;
        g_pwlo[dst] = lo;
    }
}

// ---------------------------------------------------------------------------
// hgemm via HMMA bf16 3-pass  (proven, unchanged)
// ---------------------------------------------------------------------------
#define ROWH 40   // smem row stride in halves (80B -> ldmatrix conflict-free)

__global__ __launch_bounds__(256, 2)
void hgemm_kernel(const float* __restrict__ pb) {
    __shared__ __align__(16) __nv_bfloat16 sAhi[128*ROWH], sAlo[128*ROWH];
    __shared__ __align__(16) __nv_bfloat16 sBhi[128*ROWH], sBlo[128*ROWH];

    const int tid = threadIdx.x, wid = tid >> 5, lane = tid & 31;
    const int n0 = blockIdx.x*128, m0 = blockIdx.y*128, z = blockIdx.z;
    const int wm = wid >> 1, wn = wid & 1;
    float* O = z ? g_Ht : g_Hh;
    const uint32_t* pwhiU = (const uint32_t*)(g_pwhi + (size_t)z*K3*DDIM);
    const uint32_t* pwloU = (const uint32_t*)(g_pwlo + (size_t)z*K3*DDIM);

    uint32_t* sAhiU = (uint32_t*)sAhi;
    uint32_t* sAloU = (uint32_t*)sAlo;
    uint32_t* sBhiU = (uint32_t*)sBhi;
    uint32_t* sBloU = (uint32_t*)sBlo;
    const uint32_t aHiBase = smem_u32(sAhi), aLoBase = smem_u32(sAlo);
    const uint32_t bHiBase = smem_u32(sBhi), bLoBase = smem_u32(sBlo);
    const uint32_t aRow = (uint32_t)(wm*32 + (lane & 15));
    const uint32_t aColH = (uint32_t)((lane >> 4) * 8);
    const uint32_t bRowL = (uint32_t)(lane & 7);
    const uint32_t bColH = (uint32_t)(((lane >> 3) & 1) * 8);

    float acc[2][8][4];
    #pragma unroll
    for (int t = 0; t < 2; t++)
        #pragma unroll
        for (int nt = 0; nt < 8; nt++)
            #pragma unroll
            for (int q = 0; q < 4; q++) acc[t][nt][q] = 0.f;

    for (int chunk = 0; chunk < DDIM/32; chunk++) {
        const int c0 = chunk*32;
        __syncthreads();
        #pragma unroll
        for (int it = 0; it < 8; it++) {
            int idx = tid + it*256;               // 128 rows x 16 u32
            int row = idx >> 4, cu = idx & 15;
            float2 e = *(const float2*)(g_enc + (size_t)(m0 + row)*DDIM + c0 + cu*2);
            uint32_t hi, lo;
            split2(e.x, e.y, hi, lo);
            uint32_t dst = (uint32_t)row*(ROWH/2) + cu;
            sAhiU[dst] = hi;
            sAloU[dst] = lo;
        }
        #pragma unroll
        for (int it = 0; it < 8; it++) {
            int idx = tid + it*256;               // 128 n x 16 u32
            int n = idx >> 4, cu = idx & 15;
            uint32_t src = (((uint32_t)(n0 + n)*DDIM + (uint32_t)c0) >> 1) + cu;
            uint32_t dst = (uint32_t)n*(ROWH/2) + cu;
            sBhiU[dst] = pwhiU[src];
            sBloU[dst] = pwloU[src];
        }
        __syncthreads();

        #pragma unroll
        for (int ks = 0; ks < 2; ks++) {
            uint32_t ahi[2][4], alo[2][4];
            #pragma unroll
            for (int t = 0; t < 2; t++) {
                uint32_t aoff = ((aRow + t*16)*ROWH + ks*16 + aColH) * 2;
                ldsm_x4(ahi[t], aHiBase + aoff);
                ldsm_x4(alo[t], aLoBase + aoff);
            }
            #pragma unroll
            for (int nt = 0; nt < 8; nt++) {
                uint32_t boff = (((uint32_t)(wn*64 + nt*8) + bRowL)*ROWH + ks*16 + bColH) * 2;
                uint32_t bhi[2], blo[2];
                ldsm_x2(bhi, bHiBase + boff);
                ldsm_x2(blo, bLoBase + boff);
                #pragma unroll
                for (int t = 0; t < 2; t++) {
                    mma_bf16(acc[t][nt], ahi[t], bhi);
                    mma_bf16(acc[t][nt], ahi[t], blo);
                    mma_bf16(acc[t][nt], alo[t], bhi);
                }
            }
        }
    }

    #pragma unroll
    for (int t = 0; t < 2; t++) {
        #pragma unroll
        for (int h = 0; h < 2; h++) {
            int row = m0 + wm*32 + t*16 + (lane >> 2) + h*8;
            #pragma unroll
            for (int nt = 0; nt < 8; nt++) {
                #pragma unroll
                for (int q = 0; q < 2; q++) {
                    int col = n0 + wn*64 + nt*8 + (lane & 3)*2 + q;
                    float v = acc[t][nt][h*2 + q];
                    if (z == 0) v += __ldg(pb + col);
                    O[(size_t)row*K3 + col] = v;
                }
            }
        }
    }
}

// ---------------------------------------------------------------------------
// pair GEMM via HMMA fp16 SINGLE-pass: D = act_fp16 * W_fp16
// act and relW each quantized once (independent, rms ~2^-12.3 each -> ~3e-4).
// CTA = 2 i x 96 j = 192 rows x N=72, K chunk 32, 128 threads, 3 CTAs/SM.
// B frags: 4x two-n-tile ldmatrix.x4 + 1x x2 per ks (5 LDS ops for 9 n-tiles).
// ---------------------------------------------------------------------------
#define PROWS 192

__global__ __launch_bounds__(128, 3)
void pair_kernel(const float* __restrict__ relb, float* __restrict__ out) {
    __shared__ __align__(16) __half sA[PROWS*ROWH];      // 15360 B
    __shared__ __align__(16) __half sW[NK*ROWH];         // 5760 B

    const int tid = threadIdx.x, wid = tid >> 5, lane = tid & 31;
    const int b  = blockIdx.x / (SDIM/2);          // 48 CTAs per batch
    const int i0 = (blockIdx.x - b*(SDIM/2)) * 2;

    const float* HtB  = g_Ht + (size_t)b*SDIM*K3;
    const float* Hh0  = g_Hh + (size_t)(b*SDIM + i0)*K3;
    const float* Hh1  = Hh0 + K3;

    uint32_t* sAU = (uint32_t*)sA;
    uint32_t* sWU = (uint32_t*)sW;
    const uint32_t* rwU = (const uint32_t*)g_rwhi;
    const uint32_t aBase = smem_u32(sA);
    const uint32_t bBase = smem_u32(sW);

    const uint32_t aRow  = (uint32_t)(wid*48 + (lane & 15));
    const uint32_t aColH = (uint32_t)((lane >> 4) * 8);
    // two-n-tile x4: lanes 0-7 n-rows 0-7 col 0, 8-15 rows 0-7 col 8,
    //                16-23 rows 8-15 col 0, 24-31 rows 8-15 col 8
    const uint32_t bRow  = (uint32_t)(((lane >> 4) << 3) + (lane & 7));
    const uint32_t bColH = (uint32_t)(((lane >> 3) & 1) * 8);
    // x2 (last n-tile): lanes 0-15
    const uint32_t bRowL2 = (uint32_t)(lane & 7);
    const uint32_t bColH2 = (uint32_t)(((lane >> 3) & 1) * 8);

    float acc[3][9][4];
    #pragma unroll
    for (int t = 0; t < 3; t++)
        #pragma unroll
        for (int nt = 0; nt < 9; nt++)
            #pragma unroll
            for (int q = 0; q < 4; q++) acc[t][nt][q] = 0.f;

    for (int chunk = 0; chunk < K3/32; chunk++) {
        const int c0 = chunk*32;
        __syncthreads();

        // W chunk: 72 n x 16 u32
        #pragma unroll
        for (int it = 0; it < 9; it++) {
            int idx = tid + it*128;
            int n = idx >> 4, cu = idx & 15;
            uint32_t src = (((uint32_t)n*K3 + (uint32_t)c0) >> 1) + cu;
            sWU[(uint32_t)n*(ROWH/2) + cu] = rwU[src];
        }
        // act chunk: single fp16, one Ht[j] load feeds rows j and 96+j
        #pragma unroll
        for (int it = 0; it < 12; it++) {
            int idx = tid + it*128;               // 96 j x 16 u32
            int j = idx >> 4, cu = idx & 15;
            int coff = c0 + cu*2;
            float2 ht = *(const float2*)(HtB + (size_t)j*K3 + coff);
            float2 h0 = *(const float2*)(Hh0 + coff);
            float2 h1 = *(const float2*)(Hh1 + coff);
            __half2 v0 = __float22half2_rn(make_float2(fmaxf(ht.x + h0.x, 0.f),
                                                       fmaxf(ht.y + h0.y, 0.f)));
            __half2 v1 = __float22half2_rn(make_float2(fmaxf(ht.x + h1.x, 0.f),
                                                       fmaxf(ht.y + h1.y, 0.f)));
            sAU[(uint32_t)j*(ROWH/2) + cu]          = *(uint32_t*)&v0;
            sAU[(uint32_t)(SDIM + j)*(ROWH/2) + cu] = *(uint32_t*)&v1;
        }
        __syncthreads();

        #pragma unroll
        for (int ks = 0; ks < 2; ks++) {
            uint32_t a[3][4];
            #pragma unroll
            for (int t = 0; t < 3; t++) {
                uint32_t aoff = ((aRow + t*16)*ROWH + ks*16 + aColH) * 2;
                ldsm_x4(a[t], aBase + aoff);
            }
            uint32_t bb[4][4], b8[2];
            #pragma unroll
            for (int p = 0; p < 4; p++) {
                uint32_t boff = (((uint32_t)(p*16) + bRow)*ROWH + ks*16 + bColH) * 2;
                ldsm_x4(bb[p], bBase + boff);
            }
            {
                uint32_t boff = ((64u + bRowL2)*ROWH + ks*16 + bColH2) * 2;
                ldsm_x2(b8, bBase + boff);
            }
            #pragma unroll
            for (int p = 0; p < 4; p++) {
                #pragma unroll
                for (int t = 0; t < 3; t++) {
                    mma_fp16(acc[t][2*p],     a[t], bb[p]);       // n-tile 2p
                    mma_fp16(acc[t][2*p + 1], a[t], bb[p] + 2);   // n-tile 2p+1
                }
            }
            #pragma unroll
            for (int t = 0; t < 3; t++) mma_fp16(acc[t][8], a[t], b8);
        }
    }

    // epilogue: out[b][tag][r][i][j]
    #pragma unroll
    for (int t = 0; t < 3; t++) {
        #pragma unroll
        for (int h = 0; h < 2; h++) {
            int row = wid*48 + t*16 + (lane >> 2) + h*8;   // 0..191
            int ii = row / SDIM, j = row - ii*SDIM;
            int i = i0 + ii;
            #pragma unroll
            for (int nt = 0; nt < 9; nt++) {
                #pragma unroll
                for (int q = 0; q < 2; q++) {
                    int kk = nt*8 + (lane & 3)*2 + q;
                    int r = kk / TAGS, tg = kk - r*TAGS;
                    out[(((size_t)(b*TAGS + tg)*RSTEPS + r)*SDIM + i)*(size_t)SDIM + j]
                        = acc[t][nt][h*2 + q] + __ldg(relb + kk);
                }
            }
        }
    }
}

// ---------------------------------------------------------------------------
extern "C" void kernel_launch(void* const* d_in, const int* in_sizes, int n_in,
                              void* d_out, int out_size) {
    const float* enc0 = (const float*)d_in[0];
    const float* rel  = (const float*)d_in[1];
    const float* pW   = (const float*)d_in[2];
    const float* pb   = (const float*)d_in[3];
    const float* rW   = (const float*)d_in[4];
    const float* rb   = (const float*)d_in[5];
    float* out = (float*)d_out;

    refine_pre <<<dim3(7, BDIM), 256>>>(enc0, rel);
    refine_scan<<<BDIM, 256>>>();
    refine_post<<<dim3(12, BDIM), 256>>>(enc0, rel);
    prep_relw  <<<(NK*K3 + 255)/256, 256>>>(rW);
    prep_projw <<<dim3(K3/32, (2*DDIM)/32), 256>>>(pW);
    hgemm_kernel<<<dim3(K3/128, MROWS/128, 2), 256>>>(pb);
    pair_kernel<<<BDIM*(SDIM/2), 128>>>(rb, out);
}

// round 15
// speedup vs baseline: 6.1283x; 1.1791x over previous
#include <cuda_runtime.h>
#include <cuda_bf16.h>
#include <cuda_fp16.h>
#include <cstdint>

// Problem dims
#define BDIM   8
#define SDIM   96
#define DDIM   768
#define RSTEPS 24
#define RSEQ   8
#define TAGS   3
#define K3     2304   // 3*D
#define NK     72     // R*TAG
#define MROWS  768    // B*S
#define ENC_STRIDE (SDIM*DDIM)
#define MPB    (SDIM*SDIM)

// ---- scratch (device globals; no allocation allowed) ----
__device__ float g_enc[BDIM*SDIM*DDIM];
__device__ float g_Hh [BDIM*SDIM*K3];     // enc @ Wh + proj_b
__device__ float g_Ht [BDIM*SDIM*K3];     // enc @ Wt
__device__ float g_G  [BDIM*64];
__device__ float g_S  [BDIM*RSEQ*SDIM];
__device__ float g_Ws [BDIM*RSEQ*SDIM];
__device__ __align__(16) __half g_rw[NK*K3];          // relW^T (fp16), [n][k]
__device__ __align__(16) __half g_pw[2*K3*DDIM];      // proj_W^T (fp16), [z][n][k]

__device__ __forceinline__ uint32_t smem_u32(const void* p) {
    uint32_t a;
    asm("{ .reg .u64 t; cvta.to.shared.u64 t, %1; cvt.u32.u64 %0, t; }" : "=r"(a) : "l"(p));
    return a;
}
__device__ __forceinline__ void ldsm_x4(uint32_t* r, uint32_t addr) {
    asm volatile("ldmatrix.sync.aligned.m8n8.x4.shared.b16 {%0,%1,%2,%3}, [%4];"
        : "=r"(r[0]), "=r"(r[1]), "=r"(r[2]), "=r"(r[3]) : "r"(addr));
}
__device__ __forceinline__ void ldsm_x2(uint32_t* r, uint32_t addr) {
    asm volatile("ldmatrix.sync.aligned.m8n8.x2.shared.b16 {%0,%1}, [%2];"
        : "=r"(r[0]), "=r"(r[1]) : "r"(addr));
}
__device__ __forceinline__ void mma_fp16(float* d, const uint32_t* a, const uint32_t* b) {
    asm volatile("mma.sync.aligned.m16n8k16.row.col.f32.f16.f16.f32 "
        "{%0,%1,%2,%3}, {%4,%5,%6,%7}, {%8,%9}, {%0,%1,%2,%3};"
        : "+f"(d[0]), "+f"(d[1]), "+f"(d[2]), "+f"(d[3])
        : "r"(a[0]), "r"(a[1]), "r"(a[2]), "r"(a[3]), "r"(b[0]), "r"(b[1]));
}

// ---------------------------------------------------------------------------
// refine, phase 1  (proven)
// ---------------------------------------------------------------------------
__global__ __launch_bounds__(256, 1)
void refine_pre(const float* __restrict__ enc0, const float* __restrict__ rel) {
    const int part = blockIdx.x, b = blockIdx.y;
    const int tid = threadIdx.x, warp = tid >> 5, lane = tid & 31;
    __shared__ float sA[RSEQ*DDIM];
    const float scale = rsqrtf((float)DDIM);

    for (int i = tid; i < RSEQ*DDIM; i += 256) sA[i] = rel[b*RSEQ*DDIM + i];
    __syncthreads();

    if (part == 0) {
        int pair = tid >> 2, pt = tid & 3;
        int r = pair >> 3, q = pair & 7;
        float s = 0.f;
        for (int c = pt; c < DDIM; c += 4) s += sA[r*DDIM + c] * sA[q*DDIM + c];
        s += __shfl_down_sync(0xffffffffu, s, 2, 4);
        s += __shfl_down_sync(0xffffffffu, s, 1, 4);
        if (pt == 0) g_G[b*64 + pair] = s * scale;
    } else {
        int rowbase = (part - 1) * 16;
        for (int sl = warp; sl < 16; sl += 8) {
            int row = rowbase + sl;
            const float* erow = enc0 + (b*SDIM + row)*DDIM;
            float p[8];
            #pragma unroll
            for (int r = 0; r < 8; r++) p[r] = 0.f;
            for (int c = lane; c < DDIM; c += 32) {
                float e = erow[c];
                #pragma unroll
                for (int r = 0; r < 8; r++) p[r] += sA[r*DDIM + c] * e;
            }
            #pragma unroll
            for (int r = 0; r < 8; r++) {
                float v = p[r];
                #pragma unroll
                for (int o = 16; o > 0; o >>= 1) v += __shfl_down_sync(0xffffffffu, v, o);
                if (lane == 0) g_S[b*RSEQ*SDIM + r*SDIM + row] = v * scale;
            }
        }
    }
}

// ---------------------------------------------------------------------------
// refine, phase 2  (proven)
// ---------------------------------------------------------------------------
__global__ __launch_bounds__(256, 1)
void refine_scan() {
    const int b = blockIdx.x, tid = threadIdx.x, warp = tid >> 5, lane = tid & 31;
    __shared__ float sG[64], sS[RSEQ*SDIM], sW[RSEQ*SDIM], sWs[RSEQ*SDIM];
    if (tid < 64) sG[tid] = g_G[b*64 + tid];
    for (int i = tid; i < RSEQ*SDIM; i += 256) { sS[i] = g_S[b*RSEQ*SDIM + i]; sWs[i] = 0.f; }
    __syncthreads();

    for (int t = 0; t < RSTEPS; t++) {
        {
            const float* row = sS + warp*SDIM;
            float v0 = row[lane], v1 = row[lane+32], v2 = row[lane+64];
            float m = fmaxf(v0, fmaxf(v1, v2));
            #pragma unroll
            for (int o = 16; o > 0; o >>= 1) m = fmaxf(m, __shfl_xor_sync(0xffffffffu, m, o));
            float e0 = __expf(v0 - m), e1 = __expf(v1 - m), e2 = __expf(v2 - m);
            float sum = e0 + e1 + e2;
            #pragma unroll
            for (int o = 16; o > 0; o >>= 1) sum += __shfl_xor_sync(0xffffffffu, sum, o);
            float inv = 1.f / sum;
            sW [warp*SDIM + lane]    = e0*inv;
            sW [warp*SDIM + lane+32] = e1*inv;
            sW [warp*SDIM + lane+64] = e2*inv;
            sWs[warp*SDIM + lane]    += e0*inv;
            sWs[warp*SDIM + lane+32] += e1*inv;
            sWs[warp*SDIM + lane+64] += e2*inv;
        }
        __syncthreads();
        for (int idx = tid; idx < RSEQ*SDIM; idx += 256) {
            int r = idx / SDIM, s = idx - r*SDIM;
            float acc = sS[idx];
            #pragma unroll
            for (int q = 0; q < 8; q++) acc += sG[r*8 + q] * sW[q*SDIM + s];
            sS[idx] = acc;
        }
        __syncthreads();
    }
    for (int i = tid; i < RSEQ*SDIM; i += 256) g_Ws[b*RSEQ*SDIM + i] = sWs[i];
}

// ---------------------------------------------------------------------------
// refine, phase 3  (proven)
// ---------------------------------------------------------------------------
__global__ __launch_bounds__(256, 2)
void refine_post(const float* __restrict__ enc0, const float* __restrict__ rel) {
    const int b = blockIdx.y, s0 = blockIdx.x * 8;
    const int tid = threadIdx.x;
    __shared__ float sWs[8*8];
    __shared__ float sA[RSEQ*DDIM];
    if (tid < 64) {
        int sl = tid >> 3, r = tid & 7;
        sWs[sl*8 + r] = g_Ws[b*RSEQ*SDIM + r*SDIM + s0 + sl];
    }
    for (int i = tid; i < RSEQ*DDIM; i += 256) sA[i] = rel[b*RSEQ*DDIM + i];
    __syncthreads();
    for (int idx = tid; idx < 8*DDIM; idx += 256) {
        int sl = idx / DDIM, c = idx - sl*DDIM;
        int off = (b*SDIM + s0 + sl)*DDIM + c;
        float v = enc0[off];
        #pragma unroll
        for (int r = 0; r < 8; r++) v += sWs[sl*8 + r] * sA[r*DDIM + c];
        g_enc[off] = v;
    }
}

// ---------------------------------------------------------------------------
// prep: relW^T -> single fp16 [n][k]  (proven)
// ---------------------------------------------------------------------------
__global__ __launch_bounds__(256, 4)
void prep_relw(const float* __restrict__ relW) {
    int idx = blockIdx.x * 256 + threadIdx.x;
    if (idx >= NK*K3) return;
    int n = idx / K3, k = idx - n*K3;
    g_rw[idx] = __float2half_rn(relW[(size_t)k*NK + n]);
}

// ---------------------------------------------------------------------------
// prep: proj_W^T -> single fp16 [z][n][k]  (3-pass hi/lo dropped)
// ---------------------------------------------------------------------------
__global__ __launch_bounds__(256, 4)
void prep_projw(const float* __restrict__ pW) {
    __shared__ float tile[32][33];
    const int n0 = blockIdx.x*32, k0 = blockIdx.y*32;
    const int tid = threadIdx.x;
    const int z = k0 / DDIM, kz = k0 - z*DDIM;
    #pragma unroll
    for (int it = 0; it < 4; it++) {
        int r = (tid >> 5) + it*8, c = tid & 31;
        tile[r][c] = pW[(size_t)(k0 + r)*K3 + n0 + c];
    }
    __syncthreads();
    #pragma unroll
    for (int it = 0; it < 4; it++) {
        int n = (tid >> 5) + it*8, kk = tid & 31;
        size_t dst = (size_t)z*K3*DDIM + (size_t)(n0 + n)*DDIM + kz + kk;
        g_pw[dst] = __float2half_rn(tile[kk][n]);
    }
}

// ---------------------------------------------------------------------------
// hgemm via HMMA fp16 SINGLE-pass: O[z] = enc_fp16 @ Wz_fp16 (+pb for z=0)
// grid (K3/128, MROWS/128, 2), 256 threads = 8 warps (4 m x 2 n),
// CTA tile m128 x n128, K chunk 32. B frags via two-n-tile ldmatrix.x4.
// ---------------------------------------------------------------------------
#define ROWH 40   // smem row stride in halves (80B -> ldmatrix conflict-free)

__global__ __launch_bounds__(256, 2)
void hgemm_kernel(const float* __restrict__ pb) {
    __shared__ __align__(16) __half sA[128*ROWH];   // 10240 B
    __shared__ __align__(16) __half sB[128*ROWH];   // 10240 B

    const int tid = threadIdx.x, wid = tid >> 5, lane = tid & 31;
    const int n0 = blockIdx.x*128, m0 = blockIdx.y*128, z = blockIdx.z;
    const int wm = wid >> 1, wn = wid & 1;
    float* O = z ? g_Ht : g_Hh;
    const uint32_t* pwU = (const uint32_t*)(g_pw + (size_t)z*K3*DDIM);

    uint32_t* sAU = (uint32_t*)sA;
    uint32_t* sBU = (uint32_t*)sB;
    const uint32_t aBase = smem_u32(sA);
    const uint32_t bBase = smem_u32(sB);
    const uint32_t aRow  = (uint32_t)(wm*32 + (lane & 15));
    const uint32_t aColH = (uint32_t)((lane >> 4) * 8);
    // two-n-tile x4 addressing (validated in pair_kernel)
    const uint32_t bRow  = (uint32_t)(((lane >> 4) << 3) + (lane & 7));
    const uint32_t bColH = (uint32_t)(((lane >> 3) & 1) * 8);

    float acc[2][8][4];
    #pragma unroll
    for (int t = 0; t < 2; t++)
        #pragma unroll
        for (int nt = 0; nt < 8; nt++)
            #pragma unroll
            for (int q = 0; q < 4; q++) acc[t][nt][q] = 0.f;

    for (int chunk = 0; chunk < DDIM/32; chunk++) {
        const int c0 = chunk*32;
        __syncthreads();
        #pragma unroll
        for (int it = 0; it < 8; it++) {
            int idx = tid + it*256;               // 128 rows x 16 u32
            int row = idx >> 4, cu = idx & 15;
            float2 e = *(const float2*)(g_enc + (size_t)(m0 + row)*DDIM + c0 + cu*2);
            __half2 h2 = __float22half2_rn(make_float2(e.x, e.y));
            sAU[(uint32_t)row*(ROWH/2) + cu] = *(uint32_t*)&h2;
        }
        #pragma unroll
        for (int it = 0; it < 8; it++) {
            int idx = tid + it*256;               // 128 n x 16 u32
            int n = idx >> 4, cu = idx & 15;
            uint32_t src = (((uint32_t)(n0 + n)*DDIM + (uint32_t)c0) >> 1) + cu;
            sBU[(uint32_t)n*(ROWH/2) + cu] = pwU[src];
        }
        __syncthreads();

        #pragma unroll
        for (int ks = 0; ks < 2; ks++) {
            uint32_t a[2][4];
            #pragma unroll
            for (int t = 0; t < 2; t++) {
                uint32_t aoff = ((aRow + t*16)*ROWH + ks*16 + aColH) * 2;
                ldsm_x4(a[t], aBase + aoff);
            }
            uint32_t bb[4][4];
            #pragma unroll
            for (int p = 0; p < 4; p++) {
                uint32_t boff = (((uint32_t)(wn*64 + p*16) + bRow)*ROWH + ks*16 + bColH) * 2;
                ldsm_x4(bb[p], bBase + boff);
            }
            #pragma unroll
            for (int p = 0; p < 4; p++) {
                #pragma unroll
                for (int t = 0; t < 2; t++) {
                    mma_fp16(acc[t][2*p],     a[t], bb[p]);
                    mma_fp16(acc[t][2*p + 1], a[t], bb[p] + 2);
                }
            }
        }
    }

    #pragma unroll
    for (int t = 0; t < 2; t++) {
        #pragma unroll
        for (int h = 0; h < 2; h++) {
            int row = m0 + wm*32 + t*16 + (lane >> 2) + h*8;
            #pragma unroll
            for (int nt = 0; nt < 8; nt++) {
                #pragma unroll
                for (int q = 0; q < 2; q++) {
                    int col = n0 + wn*64 + nt*8 + (lane & 3)*2 + q;
                    float v = acc[t][nt][h*2 + q];
                    if (z == 0) v += __ldg(pb + col);
                    O[(size_t)row*K3 + col] = v;
                }
            }
        }
    }
}

// ---------------------------------------------------------------------------
// pair GEMM via HMMA fp16 single-pass  (proven at 227us, unchanged)
// ---------------------------------------------------------------------------
#define PROWS 192

__global__ __launch_bounds__(128, 3)
void pair_kernel(const float* __restrict__ relb, float* __restrict__ out) {
    __shared__ __align__(16) __half sA[PROWS*ROWH];      // 15360 B
    __shared__ __align__(16) __half sW[NK*ROWH];         // 5760 B

    const int tid = threadIdx.x, wid = tid >> 5, lane = tid & 31;
    const int b  = blockIdx.x / (SDIM/2);          // 48 CTAs per batch
    const int i0 = (blockIdx.x - b*(SDIM/2)) * 2;

    const float* HtB  = g_Ht + (size_t)b*SDIM*K3;
    const float* Hh0  = g_Hh + (size_t)(b*SDIM + i0)*K3;
    const float* Hh1  = Hh0 + K3;

    uint32_t* sAU = (uint32_t*)sA;
    uint32_t* sWU = (uint32_t*)sW;
    const uint32_t* rwU = (const uint32_t*)g_rw;
    const uint32_t aBase = smem_u32(sA);
    const uint32_t bBase = smem_u32(sW);

    const uint32_t aRow  = (uint32_t)(wid*48 + (lane & 15));
    const uint32_t aColH = (uint32_t)((lane >> 4) * 8);
    const uint32_t bRow  = (uint32_t)(((lane >> 4) << 3) + (lane & 7));
    const uint32_t bColH = (uint32_t)(((lane >> 3) & 1) * 8);
    const uint32_t bRowL2 = (uint32_t)(lane & 7);
    const uint32_t bColH2 = (uint32_t)(((lane >> 3) & 1) * 8);

    float acc[3][9][4];
    #pragma unroll
    for (int t = 0; t < 3; t++)
        #pragma unroll
        for (int nt = 0; nt < 9; nt++)
            #pragma unroll
            for (int q = 0; q < 4; q++) acc[t][nt][q] = 0.f;

    for (int chunk = 0; chunk < K3/32; chunk++) {
        const int c0 = chunk*32;
        __syncthreads();

        // W chunk: 72 n x 16 u32
        #pragma unroll
        for (int it = 0; it < 9; it++) {
            int idx = tid + it*128;
            int n = idx >> 4, cu = idx & 15;
            uint32_t src = (((uint32_t)n*K3 + (uint32_t)c0) >> 1) + cu;
            sWU[(uint32_t)n*(ROWH/2) + cu] = rwU[src];
        }
        // act chunk: single fp16, one Ht[j] load feeds rows j and 96+j
        #pragma unroll
        for (int it = 0; it < 12; it++) {
            int idx = tid + it*128;               // 96 j x 16 u32
            int j = idx >> 4, cu = idx & 15;
            int coff = c0 + cu*2;
            float2 ht = *(const float2*)(HtB + (size_t)j*K3 + coff);
            float2 h0 = *(const float2*)(Hh0 + coff);
            float2 h1 = *(const float2*)(Hh1 + coff);
            __half2 v0 = __float22half2_rn(make_float2(fmaxf(ht.x + h0.x, 0.f),
                                                       fmaxf(ht.y + h0.y, 0.f)));
            __half2 v1 = __float22half2_rn(make_float2(fmaxf(ht.x + h1.x, 0.f),
                                                       fmaxf(ht.y + h1.y, 0.f)));
            sAU[(uint32_t)j*(ROWH/2) + cu]          = *(uint32_t*)&v0;
            sAU[(uint32_t)(SDIM + j)*(ROWH/2) + cu] = *(uint32_t*)&v1;
        }
        __syncthreads();

        #pragma unroll
        for (int ks = 0; ks < 2; ks++) {
            uint32_t a[3][4];
            #pragma unroll
            for (int t = 0; t < 3; t++) {
                uint32_t aoff = ((aRow + t*16)*ROWH + ks*16 + aColH) * 2;
                ldsm_x4(a[t], aBase + aoff);
            }
            uint32_t bb[4][4], b8[2];
            #pragma unroll
            for (int p = 0; p < 4; p++) {
                uint32_t boff = (((uint32_t)(p*16) + bRow)*ROWH + ks*16 + bColH) * 2;
                ldsm_x4(bb[p], bBase + boff);
            }
            {
                uint32_t boff = ((64u + bRowL2)*ROWH + ks*16 + bColH2) * 2;
                ldsm_x2(b8, bBase + boff);
            }
            #pragma unroll
            for (int p = 0; p < 4; p++) {
                #pragma unroll
                for (int t = 0; t < 3; t++) {
                    mma_fp16(acc[t][2*p],     a[t], bb[p]);
                    mma_fp16(acc[t][2*p + 1], a[t], bb[p] + 2);
                }
            }
            #pragma unroll
            for (int t = 0; t < 3; t++) mma_fp16(acc[t][8], a[t], b8);
        }
    }

    // epilogue: out[b][tag][r][i][j]
    #pragma unroll
    for (int t = 0; t < 3; t++) {
        #pragma unroll
        for (int h = 0; h < 2; h++) {
            int row = wid*48 + t*16 + (lane >> 2) + h*8;   // 0..191
            int ii = row / SDIM, j = row - ii*SDIM;
            int i = i0 + ii;
            #pragma unroll
            for (int nt = 0; nt < 9; nt++) {
                #pragma unroll
                for (int q = 0; q < 2; q++) {
                    int kk = nt*8 + (lane & 3)*2 + q;
                    int r = kk / TAGS, tg = kk - r*TAGS;
                    out[(((size_t)(b*TAGS + tg)*RSTEPS + r)*SDIM + i)*(size_t)SDIM + j]
                        = acc[t][nt][h*2 + q] + __ldg(relb + kk);
                }
            }
        }
    }
}

// ---------------------------------------------------------------------------
extern "C" void kernel_launch(void* const* d_in, const int* in_sizes, int n_in,
                              void* d_out, int out_size) {
    const float* enc0 = (const float*)d_in[0];
    const float* rel  = (const float*)d_in[1];
    const float* pW   = (const float*)d_in[2];
    const float* pb   = (const float*)d_in[3];
    const float* rW   = (const float*)d_in[4];
    const float* rb   = (const float*)d_in[5];
    float* out = (float*)d_out;

    refine_pre <<<dim3(7, BDIM), 256>>>(enc0, rel);
    refine_scan<<<BDIM, 256>>>();
    refine_post<<<dim3(12, BDIM), 256>>>(enc0, rel);
    prep_relw  <<<(NK*K3 + 255)/256, 256>>>(rW);
    prep_projw <<<dim3(K3/32, (2*DDIM)/32), 256>>>(pW);
    hgemm_kernel<<<dim3(K3/128, MROWS/128, 2), 256>>>(pb);
    pair_kernel<<<BDIM*(SDIM/2), 128>>>(rb, out);
}

// round 16
// speedup vs baseline: 6.2517x; 1.0201x over previous
#include <cuda_runtime.h>
#include <cuda_bf16.h>
#include <cuda_fp16.h>
#include <cstdint>

// Problem dims
#define BDIM   8
#define SDIM   96
#define DDIM   768
#define RSTEPS 24
#define RSEQ   8
#define TAGS   3
#define K3     2304   // 3*D
#define NK     72     // R*TAG
#define MROWS  768    // B*S
#define ENC_STRIDE (SDIM*DDIM)

// ---- scratch (device globals; no allocation allowed) ----
__device__ float g_enc[BDIM*SDIM*DDIM];
__device__ __align__(16) __half g_Hh16[BDIM*SDIM*K3];  // enc @ Wh + proj_b (fp16)
__device__ __align__(16) __half g_Ht16[BDIM*SDIM*K3];  // enc @ Wt (fp16)
__device__ float g_G  [BDIM*64];
__device__ float g_S  [BDIM*RSEQ*SDIM];
__device__ float g_Ws [BDIM*RSEQ*SDIM];
__device__ __align__(16) __half g_rw[NK*K3];          // relW^T (fp16), [n][k]
__device__ __align__(16) __half g_pw[2*K3*DDIM];      // proj_W^T (fp16), [z][n][k]

__device__ __forceinline__ uint32_t smem_u32(const void* p) {
    uint32_t a;
    asm("{ .reg .u64 t; cvta.to.shared.u64 t, %1; cvt.u32.u64 %0, t; }" : "=r"(a) : "l"(p));
    return a;
}
__device__ __forceinline__ void ldsm_x4(uint32_t* r, uint32_t addr) {
    asm volatile("ldmatrix.sync.aligned.m8n8.x4.shared.b16 {%0,%1,%2,%3}, [%4];"
        : "=r"(r[0]), "=r"(r[1]), "=r"(r[2]), "=r"(r[3]) : "r"(addr));
}
__device__ __forceinline__ void ldsm_x2(uint32_t* r, uint32_t addr) {
    asm volatile("ldmatrix.sync.aligned.m8n8.x2.shared.b16 {%0,%1}, [%2];"
        : "=r"(r[0]), "=r"(r[1]) : "r"(addr));
}
__device__ __forceinline__ void mma_fp16(float* d, const uint32_t* a, const uint32_t* b) {
    asm volatile("mma.sync.aligned.m16n8k16.row.col.f32.f16.f16.f32 "
        "{%0,%1,%2,%3}, {%4,%5,%6,%7}, {%8,%9}, {%0,%1,%2,%3};"
        : "+f"(d[0]), "+f"(d[1]), "+f"(d[2]), "+f"(d[3])
        : "r"(a[0]), "r"(a[1]), "r"(a[2]), "r"(a[3]), "r"(b[0]), "r"(b[1]));
}

// ---------------------------------------------------------------------------
// refine, phase 1  (proven)
// ---------------------------------------------------------------------------
__global__ __launch_bounds__(256, 1)
void refine_pre(const float* __restrict__ enc0, const float* __restrict__ rel) {
    const int part = blockIdx.x, b = blockIdx.y;
    const int tid = threadIdx.x, warp = tid >> 5, lane = tid & 31;
    __shared__ float sA[RSEQ*DDIM];
    const float scale = rsqrtf((float)DDIM);

    for (int i = tid; i < RSEQ*DDIM; i += 256) sA[i] = rel[b*RSEQ*DDIM + i];
    __syncthreads();

    if (part == 0) {
        int pair = tid >> 2, pt = tid & 3;
        int r = pair >> 3, q = pair & 7;
        float s = 0.f;
        for (int c = pt; c < DDIM; c += 4) s += sA[r*DDIM + c] * sA[q*DDIM + c];
        s += __shfl_down_sync(0xffffffffu, s, 2, 4);
        s += __shfl_down_sync(0xffffffffu, s, 1, 4);
        if (pt == 0) g_G[b*64 + pair] = s * scale;
    } else {
        int rowbase = (part - 1) * 16;
        for (int sl = warp; sl < 16; sl += 8) {
            int row = rowbase + sl;
            const float* erow = enc0 + (b*SDIM + row)*DDIM;
            float p[8];
            #pragma unroll
            for (int r = 0; r < 8; r++) p[r] = 0.f;
            for (int c = lane; c < DDIM; c += 32) {
                float e = erow[c];
                #pragma unroll
                for (int r = 0; r < 8; r++) p[r] += sA[r*DDIM + c] * e;
            }
            #pragma unroll
            for (int r = 0; r < 8; r++) {
                float v = p[r];
                #pragma unroll
                for (int o = 16; o > 0; o >>= 1) v += __shfl_down_sync(0xffffffffu, v, o);
                if (lane == 0) g_S[b*RSEQ*SDIM + r*SDIM + row] = v * scale;
            }
        }
    }
}

// ---------------------------------------------------------------------------
// refine, phase 2  (proven)
// ---------------------------------------------------------------------------
__global__ __launch_bounds__(256, 1)
void refine_scan() {
    const int b = blockIdx.x, tid = threadIdx.x, warp = tid >> 5, lane = tid & 31;
    __shared__ float sG[64], sS[RSEQ*SDIM], sW[RSEQ*SDIM], sWs[RSEQ*SDIM];
    if (tid < 64) sG[tid] = g_G[b*64 + tid];
    for (int i = tid; i < RSEQ*SDIM; i += 256) { sS[i] = g_S[b*RSEQ*SDIM + i]; sWs[i] = 0.f; }
    __syncthreads();

    for (int t = 0; t < RSTEPS; t++) {
        {
            const float* row = sS + warp*SDIM;
            float v0 = row[lane], v1 = row[lane+32], v2 = row[lane+64];
            float m = fmaxf(v0, fmaxf(v1, v2));
            #pragma unroll
            for (int o = 16; o > 0; o >>= 1) m = fmaxf(m, __shfl_xor_sync(0xffffffffu, m, o));
            float e0 = __expf(v0 - m), e1 = __expf(v1 - m), e2 = __expf(v2 - m);
            float sum = e0 + e1 + e2;
            #pragma unroll
            for (int o = 16; o > 0; o >>= 1) sum += __shfl_xor_sync(0xffffffffu, sum, o);
            float inv = 1.f / sum;
            sW [warp*SDIM + lane]    = e0*inv;
            sW [warp*SDIM + lane+32] = e1*inv;
            sW [warp*SDIM + lane+64] = e2*inv;
            sWs[warp*SDIM + lane]    += e0*inv;
            sWs[warp*SDIM + lane+32] += e1*inv;
            sWs[warp*SDIM + lane+64] += e2*inv;
        }
        __syncthreads();
        for (int idx = tid; idx < RSEQ*SDIM; idx += 256) {
            int r = idx / SDIM, s = idx - r*SDIM;
            float acc = sS[idx];
            #pragma unroll
            for (int q = 0; q < 8; q++) acc += sG[r*8 + q] * sW[q*SDIM + s];
            sS[idx] = acc;
        }
        __syncthreads();
    }
    for (int i = tid; i < RSEQ*SDIM; i += 256) g_Ws[b*RSEQ*SDIM + i] = sWs[i];
}

// ---------------------------------------------------------------------------
// refine, phase 3  (proven)
// ---------------------------------------------------------------------------
__global__ __launch_bounds__(256, 2)
void refine_post(const float* __restrict__ enc0, const float* __restrict__ rel) {
    const int b = blockIdx.y, s0 = blockIdx.x * 8;
    const int tid = threadIdx.x;
    __shared__ float sWs[8*8];
    __shared__ float sA[RSEQ*DDIM];
    if (tid < 64) {
        int sl = tid >> 3, r = tid & 7;
        sWs[sl*8 + r] = g_Ws[b*RSEQ*SDIM + r*SDIM + s0 + sl];
    }
    for (int i = tid; i < RSEQ*DDIM; i += 256) sA[i] = rel[b*RSEQ*DDIM + i];
    __syncthreads();
    for (int idx = tid; idx < 8*DDIM; idx += 256) {
        int sl = idx / DDIM, c = idx - sl*DDIM;
        int off = (b*SDIM + s0 + sl)*DDIM + c;
        float v = enc0[off];
        #pragma unroll
        for (int r = 0; r < 8; r++) v += sWs[sl*8 + r] * sA[r*DDIM + c];
        g_enc[off] = v;
    }
}

// ---------------------------------------------------------------------------
// prep: relW^T -> single fp16 [n][k]  (proven)
// ---------------------------------------------------------------------------
__global__ __launch_bounds__(256, 4)
void prep_relw(const float* __restrict__ relW) {
    int idx = blockIdx.x * 256 + threadIdx.x;
    if (idx >= NK*K3) return;
    int n = idx / K3, k = idx - n*K3;
    g_rw[idx] = __float2half_rn(relW[(size_t)k*NK + n]);
}

// ---------------------------------------------------------------------------
// prep: proj_W^T -> single fp16 [z][n][k]  (proven)
// ---------------------------------------------------------------------------
__global__ __launch_bounds__(256, 4)
void prep_projw(const float* __restrict__ pW) {
    __shared__ float tile[32][33];
    const int n0 = blockIdx.x*32, k0 = blockIdx.y*32;
    const int tid = threadIdx.x;
    const int z = k0 / DDIM, kz = k0 - z*DDIM;
    #pragma unroll
    for (int it = 0; it < 4; it++) {
        int r = (tid >> 5) + it*8, c = tid & 31;
        tile[r][c] = pW[(size_t)(k0 + r)*K3 + n0 + c];
    }
    __syncthreads();
    #pragma unroll
    for (int it = 0; it < 4; it++) {
        int n = (tid >> 5) + it*8, kk = tid & 31;
        size_t dst = (size_t)z*K3*DDIM + (size_t)(n0 + n)*DDIM + kz + kk;
        g_pw[dst] = __float2half_rn(tile[kk][n]);
    }
}

// ---------------------------------------------------------------------------
// hgemm via HMMA fp16 single-pass: O[z] = enc_fp16 @ Wz_fp16 (+pb for z=0)
// Core proven at 193us; epilogue now stores fp16 into g_Hh16/g_Ht16.
// ---------------------------------------------------------------------------
#define ROWH 40   // smem row stride in halves (80B -> ldmatrix conflict-free)

__global__ __launch_bounds__(256, 2)
void hgemm_kernel(const float* __restrict__ pb) {
    __shared__ __align__(16) __half sA[128*ROWH];   // 10240 B
    __shared__ __align__(16) __half sB[128*ROWH];   // 10240 B

    const int tid = threadIdx.x, wid = tid >> 5, lane = tid & 31;
    const int n0 = blockIdx.x*128, m0 = blockIdx.y*128, z = blockIdx.z;
    const int wm = wid >> 1, wn = wid & 1;
    __half* O = z ? g_Ht16 : g_Hh16;
    const uint32_t* pwU = (const uint32_t*)(g_pw + (size_t)z*K3*DDIM);

    uint32_t* sAU = (uint32_t*)sA;
    uint32_t* sBU = (uint32_t*)sB;
    const uint32_t aBase = smem_u32(sA);
    const uint32_t bBase = smem_u32(sB);
    const uint32_t aRow  = (uint32_t)(wm*32 + (lane & 15));
    const uint32_t aColH = (uint32_t)((lane >> 4) * 8);
    const uint32_t bRow  = (uint32_t)(((lane >> 4) << 3) + (lane & 7));
    const uint32_t bColH = (uint32_t)(((lane >> 3) & 1) * 8);

    float acc[2][8][4];
    #pragma unroll
    for (int t = 0; t < 2; t++)
        #pragma unroll
        for (int nt = 0; nt < 8; nt++)
            #pragma unroll
            for (int q = 0; q < 4; q++) acc[t][nt][q] = 0.f;

    for (int chunk = 0; chunk < DDIM/32; chunk++) {
        const int c0 = chunk*32;
        __syncthreads();
        #pragma unroll
        for (int it = 0; it < 8; it++) {
            int idx = tid + it*256;               // 128 rows x 16 u32
            int row = idx >> 4, cu = idx & 15;
            float2 e = *(const float2*)(g_enc + (size_t)(m0 + row)*DDIM + c0 + cu*2);
            __half2 h2 = __float22half2_rn(make_float2(e.x, e.y));
            sAU[(uint32_t)row*(ROWH/2) + cu] = *(uint32_t*)&h2;
        }
        #pragma unroll
        for (int it = 0; it < 8; it++) {
            int idx = tid + it*256;               // 128 n x 16 u32
            int n = idx >> 4, cu = idx & 15;
            uint32_t src = (((uint32_t)(n0 + n)*DDIM + (uint32_t)c0) >> 1) + cu;
            sBU[(uint32_t)n*(ROWH/2) + cu] = pwU[src];
        }
        __syncthreads();

        #pragma unroll
        for (int ks = 0; ks < 2; ks++) {
            uint32_t a[2][4];
            #pragma unroll
            for (int t = 0; t < 2; t++) {
                uint32_t aoff = ((aRow + t*16)*ROWH + ks*16 + aColH) * 2;
                ldsm_x4(a[t], aBase + aoff);
            }
            uint32_t bb[4][4];
            #pragma unroll
            for (int p = 0; p < 4; p++) {
                uint32_t boff = (((uint32_t)(wn*64 + p*16) + bRow)*ROWH + ks*16 + bColH) * 2;
                ldsm_x4(bb[p], bBase + boff);
            }
            #pragma unroll
            for (int p = 0; p < 4; p++) {
                #pragma unroll
                for (int t = 0; t < 2; t++) {
                    mma_fp16(acc[t][2*p],     a[t], bb[p]);
                    mma_fp16(acc[t][2*p + 1], a[t], bb[p] + 2);
                }
            }
        }
    }

    #pragma unroll
    for (int t = 0; t < 2; t++) {
        #pragma unroll
        for (int h = 0; h < 2; h++) {
            int row = m0 + wm*32 + t*16 + (lane >> 2) + h*8;
            #pragma unroll
            for (int nt = 0; nt < 8; nt++) {
                int col = n0 + wn*64 + nt*8 + (lane & 3)*2;
                float v0 = acc[t][nt][h*2 + 0];
                float v1 = acc[t][nt][h*2 + 1];
                if (z == 0) { v0 += __ldg(pb + col); v1 += __ldg(pb + col + 1); }
                __half2 hv = __float22half2_rn(make_float2(v0, v1));
                *(__half2*)(O + (size_t)row*K3 + col) = hv;
            }
        }
    }
}

// ---------------------------------------------------------------------------
// pair GEMM via HMMA fp16 single-pass, fp16 H inputs, K chunk 64.
// CTA = 2 i x 96 j = 192 rows x N=72, 128 threads, 3 CTAs/SM.
// Row stride 72 halves (144B): ldmatrix rows hit banks 4r mod 32 -> conflict-free.
// ---------------------------------------------------------------------------
#define PROWS 192
#define PROWH 72   // pair smem row stride in halves

__global__ __launch_bounds__(128, 3)
void pair_kernel(const float* __restrict__ relb, float* __restrict__ out) {
    __shared__ __align__(16) __half sA[PROWS*PROWH];     // 27648 B
    __shared__ __align__(16) __half sW[NK*PROWH];        // 10368 B

    const int tid = threadIdx.x, wid = tid >> 5, lane = tid & 31;
    const int b  = blockIdx.x / (SDIM/2);          // 48 CTAs per batch
    const int i0 = (blockIdx.x - b*(SDIM/2)) * 2;

    const __half* HtB = g_Ht16 + (size_t)b*SDIM*K3;
    const __half* Hh0 = g_Hh16 + (size_t)(b*SDIM + i0)*K3;
    const __half* Hh1 = Hh0 + K3;

    uint32_t* sAU = (uint32_t*)sA;
    uint32_t* sWU = (uint32_t*)sW;
    const uint32_t* rwU = (const uint32_t*)g_rw;
    const uint32_t aBase = smem_u32(sA);
    const uint32_t bBase = smem_u32(sW);

    const uint32_t aRow  = (uint32_t)(wid*48 + (lane & 15));
    const uint32_t aColH = (uint32_t)((lane >> 4) * 8);
    const uint32_t bRow  = (uint32_t)(((lane >> 4) << 3) + (lane & 7));
    const uint32_t bColH = (uint32_t)(((lane >> 3) & 1) * 8);
    const uint32_t bRowL2 = (uint32_t)(lane & 7);
    const uint32_t bColH2 = (uint32_t)(((lane >> 3) & 1) * 8);

    float acc[3][9][4];
    #pragma unroll
    for (int t = 0; t < 3; t++)
        #pragma unroll
        for (int nt = 0; nt < 9; nt++)
            #pragma unroll
            for (int q = 0; q < 4; q++) acc[t][nt][q] = 0.f;

    for (int chunk = 0; chunk < K3/64; chunk++) {
        const int c0 = chunk*64;
        __syncthreads();

        // W chunk: 72 n x 32 u32
        #pragma unroll
        for (int it = 0; it < 18; it++) {
            int idx = tid + it*128;               // 0..2303
            int n = idx >> 5, cu = idx & 31;
            uint32_t src = (((uint32_t)n*K3 + (uint32_t)c0) >> 1) + cu;
            sWU[(uint32_t)n*(PROWH/2) + cu] = rwU[src];
        }
        // act chunk: fp16 sources; one Ht[j] load feeds rows j and 96+j
        #pragma unroll
        for (int it = 0; it < 24; it++) {
            int idx = tid + it*128;               // 96 j x 32 u32
            int j = idx >> 5, cu = idx & 31;
            int coff = c0 + cu*2;                 // halves
            uint32_t htu = *(const uint32_t*)(HtB + (size_t)j*K3 + coff);
            uint32_t h0u = *(const uint32_t*)(Hh0 + coff);
            uint32_t h1u = *(const uint32_t*)(Hh1 + coff);
            float2 ht = __half22float2(*(__half2*)&htu);
            float2 h0 = __half22float2(*(__half2*)&h0u);
            float2 h1 = __half22float2(*(__half2*)&h1u);
            __half2 v0 = __float22half2_rn(make_float2(fmaxf(ht.x + h0.x, 0.f),
                                                       fmaxf(ht.y + h0.y, 0.f)));
            __half2 v1 = __float22half2_rn(make_float2(fmaxf(ht.x + h1.x, 0.f),
                                                       fmaxf(ht.y + h1.y, 0.f)));
            sAU[(uint32_t)j*(PROWH/2) + cu]          = *(uint32_t*)&v0;
            sAU[(uint32_t)(SDIM + j)*(PROWH/2) + cu] = *(uint32_t*)&v1;
        }
        __syncthreads();

        #pragma unroll
        for (int ks = 0; ks < 4; ks++) {
            uint32_t a[3][4];
            #pragma unroll
            for (int t = 0; t < 3; t++) {
                uint32_t aoff = ((aRow + t*16)*PROWH + ks*16 + aColH) * 2;
                ldsm_x4(a[t], aBase + aoff);
            }
            uint32_t bb[4][4], b8[2];
            #pragma unroll
            for (int p = 0; p < 4; p++) {
                uint32_t boff = (((uint32_t)(p*16) + bRow)*PROWH + ks*16 + bColH) * 2;
                ldsm_x4(bb[p], bBase + boff);
            }
            {
                uint32_t boff = ((64u + bRowL2)*PROWH + ks*16 + bColH2) * 2;
                ldsm_x2(b8, bBase + boff);
            }
            #pragma unroll
            for (int p = 0; p < 4; p++) {
                #pragma unroll
                for (int t = 0; t < 3; t++) {
                    mma_fp16(acc[t][2*p],     a[t], bb[p]);
                    mma_fp16(acc[t][2*p + 1], a[t], bb[p] + 2);
                }
            }
            #pragma unroll
            for (int t = 0; t < 3; t++) mma_fp16(acc[t][8], a[t], b8);
        }
    }

    // epilogue: out[b][tag][r][i][j]
    #pragma unroll
    for (int t = 0; t < 3; t++) {
        #pragma unroll
        for (int h = 0; h < 2; h++) {
            int row = wid*48 + t*16 + (lane >> 2) + h*8;   // 0..191
            int ii = row / SDIM, j = row - ii*SDIM;
            int i = i0 + ii;
            #pragma unroll
            for (int nt = 0; nt < 9; nt++) {
                #pragma unroll
                for (int q = 0; q < 2; q++) {
                    int kk = nt*8 + (lane & 3)*2 + q;
                    int r = kk / TAGS, tg = kk - r*TAGS;
                    out[(((size_t)(b*TAGS + tg)*RSTEPS + r)*SDIM + i)*(size_t)SDIM + j]
                        = acc[t][nt][h*2 + q] + __ldg(relb + kk);
                }
            }
        }
    }
}

// ---------------------------------------------------------------------------
extern "C" void kernel_launch(void* const* d_in, const int* in_sizes, int n_in,
                              void* d_out, int out_size) {
    const float* enc0 = (const float*)d_in[0];
    const float* rel  = (const float*)d_in[1];
    const float* pW   = (const float*)d_in[2];
    const float* pb   = (const float*)d_in[3];
    const float* rW   = (const float*)d_in[4];
    const float* rb   = (const float*)d_in[5];
    float* out = (float*)d_out;

    refine_pre <<<dim3(7, BDIM), 256>>>(enc0, rel);
    refine_scan<<<BDIM, 256>>>();
    refine_post<<<dim3(12, BDIM), 256>>>(enc0, rel);
    prep_relw  <<<(NK*K3 + 255)/256, 256>>>(rW);
    prep_projw <<<dim3(K3/32, (2*DDIM)/32), 256>>>(pW);
    hgemm_kernel<<<dim3(K3/128, MROWS/128, 2), 256>>>(pb);
    pair_kernel<<<BDIM*(SDIM/2), 128>>>(rb, out);
}

// round 17
// speedup vs baseline: 6.3900x; 1.0221x over previous
#include <cuda_runtime.h>
#include <cuda_bf16.h>
#include <cuda_fp16.h>
#include <cstdint>

// Problem dims
#define BDIM   8
#define SDIM   96
#define DDIM   768
#define RSTEPS 24
#define RSEQ   8
#define TAGS   3
#define K3     2304   // 3*D
#define NK     72     // R*TAG
#define MROWS  768    // B*S
#define ENC_STRIDE (SDIM*DDIM)

// ---- scratch (device globals; no allocation allowed) ----
__device__ __align__(16) __half g_enc16[BDIM*SDIM*DDIM];   // refined enc (fp16)
__device__ __align__(16) __half g_Hh16[BDIM*SDIM*K3];      // enc @ Wh + proj_b (fp16)
__device__ __align__(16) __half g_Ht16[BDIM*SDIM*K3];      // enc @ Wt (fp16)
__device__ float g_G  [BDIM*64];
__device__ float g_S  [BDIM*RSEQ*SDIM];
__device__ float g_Ws [BDIM*RSEQ*SDIM];
__device__ __align__(16) __half g_rw[NK*K3];          // relW^T (fp16), [n][k]
__device__ __align__(16) __half g_pw[2*K3*DDIM];      // proj_W^T (fp16), [z][n][k]

__device__ __forceinline__ uint32_t smem_u32(const void* p) {
    uint32_t a;
    asm("{ .reg .u64 t; cvta.to.shared.u64 t, %1; cvt.u32.u64 %0, t; }" : "=r"(a) : "l"(p));
    return a;
}
__device__ __forceinline__ void ldsm_x4(uint32_t* r, uint32_t addr) {
    asm volatile("ldmatrix.sync.aligned.m8n8.x4.shared.b16 {%0,%1,%2,%3}, [%4];"
        : "=r"(r[0]), "=r"(r[1]), "=r"(r[2]), "=r"(r[3]) : "r"(addr));
}
__device__ __forceinline__ void ldsm_x2(uint32_t* r, uint32_t addr) {
    asm volatile("ldmatrix.sync.aligned.m8n8.x2.shared.b16 {%0,%1}, [%2];"
        : "=r"(r[0]), "=r"(r[1]) : "r"(addr));
}
__device__ __forceinline__ void mma_fp16(float* d, const uint32_t* a, const uint32_t* b) {
    asm volatile("mma.sync.aligned.m16n8k16.row.col.f32.f16.f16.f32 "
        "{%0,%1,%2,%3}, {%4,%5,%6,%7}, {%8,%9}, {%0,%1,%2,%3};"
        : "+f"(d[0]), "+f"(d[1]), "+f"(d[2]), "+f"(d[3])
        : "r"(a[0]), "r"(a[1]), "r"(a[2]), "r"(a[3]), "r"(b[0]), "r"(b[1]));
}

// ---------------------------------------------------------------------------
// refine, phase 1  (proven)
// ---------------------------------------------------------------------------
__global__ __launch_bounds__(256, 1)
void refine_pre(const float* __restrict__ enc0, const float* __restrict__ rel) {
    const int part = blockIdx.x, b = blockIdx.y;
    const int tid = threadIdx.x, warp = tid >> 5, lane = tid & 31;
    __shared__ float sA[RSEQ*DDIM];
    const float scale = rsqrtf((float)DDIM);

    for (int i = tid; i < RSEQ*DDIM; i += 256) sA[i] = rel[b*RSEQ*DDIM + i];
    __syncthreads();

    if (part == 0) {
        int pair = tid >> 2, pt = tid & 3;
        int r = pair >> 3, q = pair & 7;
        float s = 0.f;
        for (int c = pt; c < DDIM; c += 4) s += sA[r*DDIM + c] * sA[q*DDIM + c];
        s += __shfl_down_sync(0xffffffffu, s, 2, 4);
        s += __shfl_down_sync(0xffffffffu, s, 1, 4);
        if (pt == 0) g_G[b*64 + pair] = s * scale;
    } else {
        int rowbase = (part - 1) * 16;
        for (int sl = warp; sl < 16; sl += 8) {
            int row = rowbase + sl;
            const float* erow = enc0 + (b*SDIM + row)*DDIM;
            float p[8];
            #pragma unroll
            for (int r = 0; r < 8; r++) p[r] = 0.f;
            for (int c = lane; c < DDIM; c += 32) {
                float e = erow[c];
                #pragma unroll
                for (int r = 0; r < 8; r++) p[r] += sA[r*DDIM + c] * e;
            }
            #pragma unroll
            for (int r = 0; r < 8; r++) {
                float v = p[r];
                #pragma unroll
                for (int o = 16; o > 0; o >>= 1) v += __shfl_down_sync(0xffffffffu, v, o);
                if (lane == 0) g_S[b*RSEQ*SDIM + r*SDIM + row] = v * scale;
            }
        }
    }
}

// ---------------------------------------------------------------------------
// refine, phase 2  (proven)
// ---------------------------------------------------------------------------
__global__ __launch_bounds__(256, 1)
void refine_scan() {
    const int b = blockIdx.x, tid = threadIdx.x, warp = tid >> 5, lane = tid & 31;
    __shared__ float sG[64], sS[RSEQ*SDIM], sW[RSEQ*SDIM], sWs[RSEQ*SDIM];
    if (tid < 64) sG[tid] = g_G[b*64 + tid];
    for (int i = tid; i < RSEQ*SDIM; i += 256) { sS[i] = g_S[b*RSEQ*SDIM + i]; sWs[i] = 0.f; }
    __syncthreads();

    for (int t = 0; t < RSTEPS; t++) {
        {
            const float* row = sS + warp*SDIM;
            float v0 = row[lane], v1 = row[lane+32], v2 = row[lane+64];
            float m = fmaxf(v0, fmaxf(v1, v2));
            #pragma unroll
            for (int o = 16; o > 0; o >>= 1) m = fmaxf(m, __shfl_xor_sync(0xffffffffu, m, o));
            float e0 = __expf(v0 - m), e1 = __expf(v1 - m), e2 = __expf(v2 - m);
            float sum = e0 + e1 + e2;
            #pragma unroll
            for (int o = 16; o > 0; o >>= 1) sum += __shfl_xor_sync(0xffffffffu, sum, o);
            float inv = 1.f / sum;
            sW [warp*SDIM + lane]    = e0*inv;
            sW [warp*SDIM + lane+32] = e1*inv;
            sW [warp*SDIM + lane+64] = e2*inv;
            sWs[warp*SDIM + lane]    += e0*inv;
            sWs[warp*SDIM + lane+32] += e1*inv;
            sWs[warp*SDIM + lane+64] += e2*inv;
        }
        __syncthreads();
        for (int idx = tid; idx < RSEQ*SDIM; idx += 256) {
            int r = idx / SDIM, s = idx - r*SDIM;
            float acc = sS[idx];
            #pragma unroll
            for (int q = 0; q < 8; q++) acc += sG[r*8 + q] * sW[q*SDIM + s];
            sS[idx] = acc;
        }
        __syncthreads();
    }
    for (int i = tid; i < RSEQ*SDIM; i += 256) g_Ws[b*RSEQ*SDIM + i] = sWs[i];
}

// ---------------------------------------------------------------------------
// refine, phase 3: enc16 = fp16(enc0 + Ws^T @ A)  (now emits fp16 directly)
// ---------------------------------------------------------------------------
__global__ __launch_bounds__(256, 2)
void refine_post(const float* __restrict__ enc0, const float* __restrict__ rel) {
    const int b = blockIdx.y, s0 = blockIdx.x * 8;
    const int tid = threadIdx.x;
    __shared__ float sWs[8*8];
    __shared__ float sA[RSEQ*DDIM];
    if (tid < 64) {
        int sl = tid >> 3, r = tid & 7;
        sWs[sl*8 + r] = g_Ws[b*RSEQ*SDIM + r*SDIM + s0 + sl];
    }
    for (int i = tid; i < RSEQ*DDIM; i += 256) sA[i] = rel[b*RSEQ*DDIM + i];
    __syncthreads();
    // 2 floats per thread -> __half2 store
    for (int idx = tid; idx < 8*DDIM/2; idx += 256) {
        int e2 = idx*2;
        int sl = e2 / DDIM, c = e2 - sl*DDIM;
        int off = (b*SDIM + s0 + sl)*DDIM + c;
        float v0 = enc0[off], v1 = enc0[off + 1];
        #pragma unroll
        for (int r = 0; r < 8; r++) {
            float w = sWs[sl*8 + r];
            v0 += w * sA[r*DDIM + c];
            v1 += w * sA[r*DDIM + c + 1];
        }
        *(__half2*)(g_enc16 + off) = __float22half2_rn(make_float2(v0, v1));
    }
}

// ---------------------------------------------------------------------------
// prep_weights: fused relW^T and proj_W^T -> fp16 transposed layouts
//   blocks [0, 648):       relW^T  -> g_rw  [n][k]
//   blocks [648, 4104):    proj_W^T -> g_pw [z][n][k]  (smem-tiled transpose)
// ---------------------------------------------------------------------------
#define PREP_RELW_BLKS 648
#define PREP_TOTAL     (PREP_RELW_BLKS + (K3/32)*((2*DDIM)/32))

__global__ __launch_bounds__(256)
void prep_weights(const float* __restrict__ relW, const float* __restrict__ pW) {
    __shared__ float tile[32][33];
    const int blk = blockIdx.x, tid = threadIdx.x;

    if (blk < PREP_RELW_BLKS) {
        int idx = blk * 256 + tid;
        if (idx < NK*K3) {
            int n = idx / K3, k = idx - n*K3;
            g_rw[idx] = __float2half_rn(relW[(size_t)k*NK + n]);
        }
    } else {
        const int t  = blk - PREP_RELW_BLKS;
        const int n0 = (t % (K3/32)) * 32;
        const int k0 = (t / (K3/32)) * 32;
        const int z  = k0 / DDIM, kz = k0 - z*DDIM;
        #pragma unroll
        for (int it = 0; it < 4; it++) {
            int r = (tid >> 5) + it*8, c = tid & 31;
            tile[r][c] = pW[(size_t)(k0 + r)*K3 + n0 + c];
        }
        __syncthreads();
        #pragma unroll
        for (int it = 0; it < 4; it++) {
            int n = (tid >> 5) + it*8, kk = tid & 31;
            size_t dst = (size_t)z*K3*DDIM + (size_t)(n0 + n)*DDIM + kz + kk;
            g_pw[dst] = __float2half_rn(tile[kk][n]);
        }
    }
}

// ---------------------------------------------------------------------------
// hgemm via HMMA fp16 single-pass, fp16 A source, K chunk 64.
// grid (K3/128, MROWS/128, 2), 256 threads = 8 warps (4 m x 2 n).
// Row stride 72 halves (proven in pair_kernel). smem 36.9 KB, 2 CTAs/SM.
// ---------------------------------------------------------------------------
#define HROWH 72

__global__ __launch_bounds__(256, 2)
void hgemm_kernel(const float* __restrict__ pb) {
    __shared__ __align__(16) __half sA[128*HROWH];   // 18432 B
    __shared__ __align__(16) __half sB[128*HROWH];   // 18432 B

    const int tid = threadIdx.x, wid = tid >> 5, lane = tid & 31;
    const int n0 = blockIdx.x*128, m0 = blockIdx.y*128, z = blockIdx.z;
    const int wm = wid >> 1, wn = wid & 1;
    __half* O = z ? g_Ht16 : g_Hh16;
    const uint32_t* encU = (const uint32_t*)g_enc16;
    const uint32_t* pwU  = (const uint32_t*)(g_pw + (size_t)z*K3*DDIM);

    uint32_t* sAU = (uint32_t*)sA;
    uint32_t* sBU = (uint32_t*)sB;
    const uint32_t aBase = smem_u32(sA);
    const uint32_t bBase = smem_u32(sB);
    const uint32_t aRow  = (uint32_t)(wm*32 + (lane & 15));
    const uint32_t aColH = (uint32_t)((lane >> 4) * 8);
    const uint32_t bRow  = (uint32_t)(((lane >> 4) << 3) + (lane & 7));
    const uint32_t bColH = (uint32_t)(((lane >> 3) & 1) * 8);

    float acc[2][8][4];
    #pragma unroll
    for (int t = 0; t < 2; t++)
        #pragma unroll
        for (int nt = 0; nt < 8; nt++)
            #pragma unroll
            for (int q = 0; q < 4; q++) acc[t][nt][q] = 0.f;

    for (int chunk = 0; chunk < DDIM/64; chunk++) {
        const int c0 = chunk*64;
        __syncthreads();
        #pragma unroll
        for (int it = 0; it < 16; it++) {
            int idx = tid + it*256;               // 128 rows x 32 u32
            int row = idx >> 5, cu = idx & 31;
            uint32_t src = (((uint32_t)(m0 + row)*DDIM + (uint32_t)c0) >> 1) + cu;
            sAU[(uint32_t)row*(HROWH/2) + cu] = encU[src];
        }
        #pragma unroll
        for (int it = 0; it < 16; it++) {
            int idx = tid + it*256;               // 128 n x 32 u32
            int n = idx >> 5, cu = idx & 31;
            uint32_t src = (((uint32_t)(n0 + n)*DDIM + (uint32_t)c0) >> 1) + cu;
            sBU[(uint32_t)n*(HROWH/2) + cu] = pwU[src];
        }
        __syncthreads();

        #pragma unroll
        for (int ks = 0; ks < 4; ks++) {
            uint32_t a[2][4];
            #pragma unroll
            for (int t = 0; t < 2; t++) {
                uint32_t aoff = ((aRow + t*16)*HROWH + ks*16 + aColH) * 2;
                ldsm_x4(a[t], aBase + aoff);
            }
            uint32_t bb[4][4];
            #pragma unroll
            for (int p = 0; p < 4; p++) {
                uint32_t boff = (((uint32_t)(wn*64 + p*16) + bRow)*HROWH + ks*16 + bColH) * 2;
                ldsm_x4(bb[p], bBase + boff);
            }
            #pragma unroll
            for (int p = 0; p < 4; p++) {
                #pragma unroll
                for (int t = 0; t < 2; t++) {
                    mma_fp16(acc[t][2*p],     a[t], bb[p]);
                    mma_fp16(acc[t][2*p + 1], a[t], bb[p] + 2);
                }
            }
        }
    }

    #pragma unroll
    for (int t = 0; t < 2; t++) {
        #pragma unroll
        for (int h = 0; h < 2; h++) {
            int row = m0 + wm*32 + t*16 + (lane >> 2) + h*8;
            #pragma unroll
            for (int nt = 0; nt < 8; nt++) {
                int col = n0 + wn*64 + nt*8 + (lane & 3)*2;
                float v0 = acc[t][nt][h*2 + 0];
                float v1 = acc[t][nt][h*2 + 1];
                if (z == 0) { v0 += __ldg(pb + col); v1 += __ldg(pb + col + 1); }
                __half2 hv = __float22half2_rn(make_float2(v0, v1));
                *(__half2*)(O + (size_t)row*K3 + col) = hv;
            }
        }
    }
}

// ---------------------------------------------------------------------------
// pair GEMM via HMMA fp16 single-pass, fp16 H inputs, K chunk 64.
// (proven at 189us, unchanged)
// ---------------------------------------------------------------------------
#define PROWS 192
#define PROWH 72

__global__ __launch_bounds__(128, 3)
void pair_kernel(const float* __restrict__ relb, float* __restrict__ out) {
    __shared__ __align__(16) __half sA[PROWS*PROWH];     // 27648 B
    __shared__ __align__(16) __half sW[NK*PROWH];        // 10368 B

    const int tid = threadIdx.x, wid = tid >> 5, lane = tid & 31;
    const int b  = blockIdx.x / (SDIM/2);          // 48 CTAs per batch
    const int i0 = (blockIdx.x - b*(SDIM/2)) * 2;

    const __half* HtB = g_Ht16 + (size_t)b*SDIM*K3;
    const __half* Hh0 = g_Hh16 + (size_t)(b*SDIM + i0)*K3;
    const __half* Hh1 = Hh0 + K3;

    uint32_t* sAU = (uint32_t*)sA;
    uint32_t* sWU = (uint32_t*)sW;
    const uint32_t* rwU = (const uint32_t*)g_rw;
    const uint32_t aBase = smem_u32(sA);
    const uint32_t bBase = smem_u32(sW);

    const uint32_t aRow  = (uint32_t)(wid*48 + (lane & 15));
    const uint32_t aColH = (uint32_t)((lane >> 4) * 8);
    const uint32_t bRow  = (uint32_t)(((lane >> 4) << 3) + (lane & 7));
    const uint32_t bColH = (uint32_t)(((lane >> 3) & 1) * 8);
    const uint32_t bRowL2 = (uint32_t)(lane & 7);
    const uint32_t bColH2 = (uint32_t)(((lane >> 3) & 1) * 8);

    float acc[3][9][4];
    #pragma unroll
    for (int t = 0; t < 3; t++)
        #pragma unroll
        for (int nt = 0; nt < 9; nt++)
            #pragma unroll
            for (int q = 0; q < 4; q++) acc[t][nt][q] = 0.f;

    for (int chunk = 0; chunk < K3/64; chunk++) {
        const int c0 = chunk*64;
        __syncthreads();

        // W chunk: 72 n x 32 u32
        #pragma unroll
        for (int it = 0; it < 18; it++) {
            int idx = tid + it*128;               // 0..2303
            int n = idx >> 5, cu = idx & 31;
            uint32_t src = (((uint32_t)n*K3 + (uint32_t)c0) >> 1) + cu;
            sWU[(uint32_t)n*(PROWH/2) + cu] = rwU[src];
        }
        // act chunk: fp16 sources; one Ht[j] load feeds rows j and 96+j
        #pragma unroll
        for (int it = 0; it < 24; it++) {
            int idx = tid + it*128;               // 96 j x 32 u32
            int j = idx >> 5, cu = idx & 31;
            int coff = c0 + cu*2;                 // halves
            uint32_t htu = *(const uint32_t*)(HtB + (size_t)j*K3 + coff);
            uint32_t h0u = *(const uint32_t*)(Hh0 + coff);
            uint32_t h1u = *(const uint32_t*)(Hh1 + coff);
            float2 ht = __half22float2(*(__half2*)&htu);
            float2 h0 = __half22float2(*(__half2*)&h0u);
            float2 h1 = __half22float2(*(__half2*)&h1u);
            __half2 v0 = __float22half2_rn(make_float2(fmaxf(ht.x + h0.x, 0.f),
                                                       fmaxf(ht.y + h0.y, 0.f)));
            __half2 v1 = __float22half2_rn(make_float2(fmaxf(ht.x + h1.x, 0.f),
                                                       fmaxf(ht.y + h1.y, 0.f)));
            sAU[(uint32_t)j*(PROWH/2) + cu]          = *(uint32_t*)&v0;
            sAU[(uint32_t)(SDIM + j)*(PROWH/2) + cu] = *(uint32_t*)&v1;
        }
        __syncthreads();

        #pragma unroll
        for (int ks = 0; ks < 4; ks++) {
            uint32_t a[3][4];
            #pragma unroll
            for (int t = 0; t < 3; t++) {
                uint32_t aoff = ((aRow + t*16)*PROWH + ks*16 + aColH) * 2;
                ldsm_x4(a[t], aBase + aoff);
            }
            uint32_t bb[4][4], b8[2];
            #pragma unroll
            for (int p = 0; p < 4; p++) {
                uint32_t boff = (((uint32_t)(p*16) + bRow)*PROWH + ks*16 + bColH) * 2;
                ldsm_x4(bb[p], bBase + boff);
            }
            {
                uint32_t boff = ((64u + bRowL2)*PROWH + ks*16 + bColH2) * 2;
                ldsm_x2(b8, bBase + boff);
            }
            #pragma unroll
            for (int p = 0; p < 4; p++) {
                #pragma unroll
                for (int t = 0; t < 3; t++) {
                    mma_fp16(acc[t][2*p],     a[t], bb[p]);
                    mma_fp16(acc[t][2*p + 1], a[t], bb[p] + 2);
                }
            }
            #pragma unroll
            for (int t = 0; t < 3; t++) mma_fp16(acc[t][8], a[t], b8);
        }
    }

    // epilogue: out[b][tag][r][i][j]
    #pragma unroll
    for (int t = 0; t < 3; t++) {
        #pragma unroll
        for (int h = 0; h < 2; h++) {
            int row = wid*48 + t*16 + (lane >> 2) + h*8;   // 0..191
            int ii = row / SDIM, j = row - ii*SDIM;
            int i = i0 + ii;
            #pragma unroll
            for (int nt = 0; nt < 9; nt++) {
                #pragma unroll
                for (int q = 0; q < 2; q++) {
                    int kk = nt*8 + (lane & 3)*2 + q;
                    int r = kk / TAGS, tg = kk - r*TAGS;
                    out[(((size_t)(b*TAGS + tg)*RSTEPS + r)*SDIM + i)*(size_t)SDIM + j]
                        = acc[t][nt][h*2 + q] + __ldg(relb + kk);
                }
            }
        }
    }
}

// ---------------------------------------------------------------------------
extern "C" void kernel_launch(void* const* d_in, const int* in_sizes, int n_in,
                              void* d_out, int out_size) {
    const float* enc0 = (const float*)d_in[0];
    const float* rel  = (const float*)d_in[1];
    const float* pW   = (const float*)d_in[2];
    const float* pb   = (const float*)d_in[3];
    const float* rW   = (const float*)d_in[4];
    const float* rb   = (const float*)d_in[5];
    float* out = (float*)d_out;

    refine_pre  <<<dim3(7, BDIM), 256>>>(enc0, rel);
    refine_scan <<<BDIM, 256>>>();
    refine_post <<<dim3(12, BDIM), 256>>>(enc0, rel);
    prep_weights<<<PREP_TOTAL, 256>>>(rW, pW);
    hgemm_kernel<<<dim3(K3/128, MROWS/128, 2), 256>>>(pb);
    pair_kernel <<<BDIM*(SDIM/2), 128>>>(rb, out);
}